// round 11
// baseline (speedup 1.0000x reference)
#include <cuda_runtime.h>
#include <cstdint>
#include <cstddef>

// ---------------------------------------------------------------------------
// Problem constants (fixed shapes per reference)
// ---------------------------------------------------------------------------
#define NU    100000
#define NI    50000
#define KDIM  256
#define MSGD  128
#define OUTD  128
#define RREL  5
#define NE    1000000
#define NCOMB (RREL * OUTD)   // 640

// ---------------------------------------------------------------------------
// Static device scratch (no runtime allocation allowed)
// ---------------------------------------------------------------------------
static __device__ float g_xu[(size_t)NU * NCOMB];     // 256 MB: per-relation user messages (post W-combine)
static __device__ float g_xi[(size_t)NI * NCOMB];     // 128 MB: per-relation item messages
static __device__ float g_accu[(size_t)NU * OUTD];    // 51.2 MB
static __device__ float g_acci[(size_t)NI * OUTD];    // 25.6 MB
static __device__ float g_wcu[KDIM * NCOMB];          // W_u[r] @ Wi_fc_r   (user feats -> item outputs)
static __device__ float g_wci[KDIM * NCOMB];          // W_i[r] @ Wu_fc_r   (item feats -> user outputs)

// ---------------------------------------------------------------------------
// Kernel 1: combine weights  Wc[k][r*128+o] = sum_m W[r,k,m] * Wfc[r*128+m, o]
// ---------------------------------------------------------------------------
__global__ void combine_w_kernel(const float* __restrict__ W,
                                 const float* __restrict__ Wfc,
                                 float* __restrict__ Wc)
{
    int idx = blockIdx.x * blockDim.x + threadIdx.x;
    if (idx >= KDIM * NCOMB) return;
    int k = idx / NCOMB;
    int c = idx - k * NCOMB;
    int r = c / OUTD;
    int o = c - r * OUTD;
    const float* wrow = W + ((size_t)r * KDIM + k) * MSGD;
    const float* fc   = Wfc + ((size_t)r * MSGD) * OUTD + o;
    float s = 0.f;
#pragma unroll 8
    for (int m = 0; m < MSGD; ++m)
        s += wrow[m] * fc[(size_t)m * OUTD];
    Wc[idx] = s;
}

// ---------------------------------------------------------------------------
// Kernel 2: zero accumulators
// ---------------------------------------------------------------------------
__global__ void zero_kernel(float4* __restrict__ p, int n4)
{
    int i = blockIdx.x * blockDim.x + threadIdx.x;
    if (i < n4) p[i] = make_float4(0.f, 0.f, 0.f, 0.f);
}

// ---------------------------------------------------------------------------
// Kernel 3: SGEMM  X[m, :] = (A[m, :256] @ B[256, 640]) * cj[m]
// 128x128 block tile, BK=8, 8x8 per-thread register tile, 256 threads.
// ---------------------------------------------------------------------------
__global__ __launch_bounds__(256, 1) void gemm_scale_kernel(
    const float* __restrict__ A,   // [M, 256]
    const float* __restrict__ B,   // [256, 640]
    const float* __restrict__ cj,  // [M]
    float* __restrict__ X,         // [M, 640]
    int M)
{
    constexpr int K = KDIM;
    constexpr int N = NCOMB;
    __shared__ float As[8][128];
    __shared__ float Bs[8][128];

    const int t = threadIdx.x;
    const int rowBase = blockIdx.y * 128;
    const int colBase = blockIdx.x * 128;

    const int aRow = t >> 1;            // 0..127
    const int aCol = (t & 1) << 2;      // 0 or 4
    const int bRow = t >> 5;            // 0..7
    const int bCol = (t & 31) << 2;     // 0..124

    const int tx = (t & 15) << 3;       // col offset in tile
    const int ty = (t >> 4) << 3;       // row offset in tile

    float acc[8][8];
#pragma unroll
    for (int i = 0; i < 8; ++i)
#pragma unroll
        for (int j = 0; j < 8; ++j) acc[i][j] = 0.f;

    const int grA = rowBase + aRow;
    const bool aValid = (grA < M);

    for (int k0 = 0; k0 < K; k0 += 8) {
        float4 av = make_float4(0.f, 0.f, 0.f, 0.f);
        if (aValid)
            av = *(const float4*)(A + (size_t)grA * K + k0 + aCol);
        As[aCol + 0][aRow] = av.x;
        As[aCol + 1][aRow] = av.y;
        As[aCol + 2][aRow] = av.z;
        As[aCol + 3][aRow] = av.w;

        float4 bv = *(const float4*)(B + (size_t)(k0 + bRow) * N + colBase + bCol);
        *(float4*)&Bs[bRow][bCol] = bv;

        __syncthreads();

#pragma unroll
        for (int k = 0; k < 8; ++k) {
            float a[8], b[8];
            *(float4*)&a[0] = *(const float4*)&As[k][ty];
            *(float4*)&a[4] = *(const float4*)&As[k][ty + 4];
            *(float4*)&b[0] = *(const float4*)&Bs[k][tx];
            *(float4*)&b[4] = *(const float4*)&Bs[k][tx + 4];
#pragma unroll
            for (int i = 0; i < 8; ++i)
#pragma unroll
                for (int j = 0; j < 8; ++j)
                    acc[i][j] += a[i] * b[j];
        }
        __syncthreads();
    }

#pragma unroll
    for (int i = 0; i < 8; ++i) {
        int gr = rowBase + ty + i;
        if (gr < M) {
            float c = cj[gr];
            float4 o0, o1;
            o0.x = acc[i][0] * c; o0.y = acc[i][1] * c;
            o0.z = acc[i][2] * c; o0.w = acc[i][3] * c;
            o1.x = acc[i][4] * c; o1.y = acc[i][5] * c;
            o1.z = acc[i][6] * c; o1.w = acc[i][7] * c;
            *(float4*)(X + (size_t)gr * N + colBase + tx)     = o0;
            *(float4*)(X + (size_t)gr * N + colBase + tx + 4) = o1;
        }
    }
}

// ---------------------------------------------------------------------------
// Kernel 4: edge scatter. One warp per edge: gather 128-float message row,
// vector-reduce-add into destination accumulator row.
// edge arrays are [R, E] flattened, so the flat warp index == r*NE + e.
// ---------------------------------------------------------------------------
__global__ __launch_bounds__(256) void scatter_kernel(
    const float* __restrict__ X,      // [n_src, 640]
    const int* __restrict__ esrc,     // [R*E]
    const int* __restrict__ edst,     // [R*E]
    float* __restrict__ acc)          // [n_dst, 128]
{
    long long w = (long long)blockIdx.x * 8 + (threadIdx.x >> 5);
    if (w >= (long long)RREL * NE) return;
    int lane = threadIdx.x & 31;
    int r = (int)(w / NE);
    int src = esrc[w];
    int dst = edst[w];

    const float4* xp = (const float4*)(X + (size_t)src * NCOMB + (size_t)r * OUTD);
    float4 v = xp[lane];

    float* ap = acc + (size_t)dst * OUTD + lane * 4;
    asm volatile("red.global.add.v4.f32 [%0], {%1, %2, %3, %4};"
                 :: "l"(ap), "f"(v.x), "f"(v.y), "f"(v.z), "f"(v.w)
                 : "memory");
}

// ---------------------------------------------------------------------------
// Kernel 5: finalize  out[n, o] = acc[n, o] * ci[n] + b[o]
// ---------------------------------------------------------------------------
__global__ void finalize_kernel(const float* __restrict__ acc,
                                const float* __restrict__ ci,
                                const float* __restrict__ b,
                                float* __restrict__ out, int n)
{
    int idx = blockIdx.x * blockDim.x + threadIdx.x;
    if (idx >= n * OUTD) return;
    int row = idx >> 7;
    int o = idx & (OUTD - 1);
    out[idx] = acc[idx] * ci[row] + b[o];
}

// ---------------------------------------------------------------------------
// Host launcher
// ---------------------------------------------------------------------------
extern "C" void kernel_launch(void* const* d_in, const int* in_sizes, int n_in,
                              void* d_out, int out_size)
{
    const float* ufeat   = (const float*)d_in[0];
    const float* ifeat   = (const float*)d_in[1];
    const float* cj_user = (const float*)d_in[2];
    const float* ci_user = (const float*)d_in[3];
    const float* cj_item = (const float*)d_in[4];
    const float* ci_item = (const float*)d_in[5];
    const float* W_u     = (const float*)d_in[6];
    const float* W_i     = (const float*)d_in[7];
    const float* Wu_fc   = (const float*)d_in[8];
    const float* bu      = (const float*)d_in[9];
    const float* Wi_fc   = (const float*)d_in[10];
    const float* bi      = (const float*)d_in[11];
    const int*   edge_u  = (const int*)d_in[12];
    const int*   edge_i  = (const int*)d_in[13];
    float* out = (float*)d_out;

    float *xu, *xi, *accu, *acci, *wcu, *wci;
    cudaGetSymbolAddress((void**)&xu,   g_xu);
    cudaGetSymbolAddress((void**)&xi,   g_xi);
    cudaGetSymbolAddress((void**)&accu, g_accu);
    cudaGetSymbolAddress((void**)&acci, g_acci);
    cudaGetSymbolAddress((void**)&wcu,  g_wcu);
    cudaGetSymbolAddress((void**)&wci,  g_wci);

    // 1) Fold per-relation projection into FC slice.
    //    user messages feed ITEM outputs -> Wi_fc; item messages feed USER outputs -> Wu_fc.
    int ctotal = KDIM * NCOMB;
    combine_w_kernel<<<(ctotal + 255) / 256, 256>>>(W_u, Wi_fc, wcu);
    combine_w_kernel<<<(ctotal + 255) / 256, 256>>>(W_i, Wu_fc, wci);

    // 2) Zero accumulators.
    zero_kernel<<<((NU * OUTD / 4) + 255) / 256, 256>>>((float4*)accu, NU * OUTD / 4);
    zero_kernel<<<((NI * OUTD / 4) + 255) / 256, 256>>>((float4*)acci, NI * OUTD / 4);

    // 3) Fused message GEMMs (with cj source scaling folded into the store).
    dim3 gu(NCOMB / 128, (NU + 127) / 128);
    gemm_scale_kernel<<<gu, 256>>>(ufeat, wcu, cj_user, xu, NU);
    dim3 gi(NCOMB / 128, (NI + 127) / 128);
    gemm_scale_kernel<<<gi, 256>>>(ifeat, wci, cj_item, xi, NI);

    // 4) Edge scatter, both directions (all 5 relations accumulate into one 128-wide buffer).
    long long totw = (long long)RREL * NE;
    int sblocks = (int)((totw * 32 + 255) / 256);
    scatter_kernel<<<sblocks, 256>>>(xu, edge_u, edge_i, acci);  // user -> item
    scatter_kernel<<<sblocks, 256>>>(xi, edge_i, edge_u, accu);  // item -> user

    // 5) Finalize: destination ci scaling + bias. Output = [new_u | new_i].
    finalize_kernel<<<((NU * OUTD) + 255) / 256, 256>>>(accu, ci_user, bu, out, NU);
    finalize_kernel<<<((NI * OUTD) + 255) / 256, 256>>>(acci, ci_item, bi,
                                                        out + (size_t)NU * OUTD, NI);
}

// round 12
// speedup vs baseline: 1.4826x; 1.4826x over previous
#include <cuda_runtime.h>
#include <cstdint>
#include <cstddef>

// ---------------------------------------------------------------------------
// Problem constants (fixed shapes per reference)
// ---------------------------------------------------------------------------
#define NU    100000
#define NI    50000
#define KDIM  256
#define MSGD  128
#define OUTD  128
#define RREL  5
#define NE    1000000
#define NCOMB (RREL * OUTD)   // 640

// ---------------------------------------------------------------------------
// Static device scratch (no runtime allocation allowed)
// ---------------------------------------------------------------------------
static __device__ float g_xu[(size_t)NU * NCOMB];
static __device__ float g_xi[(size_t)NI * NCOMB];
static __device__ float g_accu[(size_t)NU * OUTD];
static __device__ float g_acci[(size_t)NI * OUTD];
static __device__ float g_wcu[KDIM * NCOMB];
static __device__ float g_wci[KDIM * NCOMB];

// ---------------------------------------------------------------------------
// Kernel 1: combine weights  Wc[k][r*128+o] = sum_m W[r,k,m] * Wfc[r*128+m, o]
// ---------------------------------------------------------------------------
__global__ void combine_w_kernel(const float* __restrict__ W,
                                 const float* __restrict__ Wfc,
                                 float* __restrict__ Wc)
{
    int idx = blockIdx.x * blockDim.x + threadIdx.x;
    if (idx >= KDIM * NCOMB) return;
    int k = idx / NCOMB;
    int c = idx - k * NCOMB;
    int r = c / OUTD;
    int o = c - r * OUTD;
    const float* wrow = W + ((size_t)r * KDIM + k) * MSGD;
    const float* fc   = Wfc + ((size_t)r * MSGD) * OUTD + o;
    float s = 0.f;
#pragma unroll 8
    for (int m = 0; m < MSGD; ++m)
        s += wrow[m] * fc[(size_t)m * OUTD];
    Wc[idx] = s;
}

// ---------------------------------------------------------------------------
// Kernel 2: zero accumulators
// ---------------------------------------------------------------------------
__global__ void zero_kernel(float4* __restrict__ p, int n4)
{
    int i = blockIdx.x * blockDim.x + threadIdx.x;
    if (i < n4) p[i] = make_float4(0.f, 0.f, 0.f, 0.f);
}

// ---------------------------------------------------------------------------
// TF32 helpers
// ---------------------------------------------------------------------------
__device__ __forceinline__ float to_tf32(float x)
{
    uint32_t u;
    asm("cvt.rna.tf32.f32 %0, %1;" : "=r"(u) : "f"(x));
    return __uint_as_float(u);
}

__device__ __forceinline__ float4 tf32x4(float4 v)
{
    v.x = to_tf32(v.x); v.y = to_tf32(v.y);
    v.z = to_tf32(v.z); v.w = to_tf32(v.w);
    return v;
}

// ---------------------------------------------------------------------------
// Kernel 3: TF32 tensor-core GEMM  X[m,:] = (A[m,:256] @ B[256,640]) * cj[m]
// Block tile 128x128, BK=16, double-buffered smem.
// 8 warps in a 2x4 grid -> warp tile 64x32 = 4x4 m16n8k8 mma tiles.
// A fragments via ldmatrix.x4.b16 (tf32 = 2x b16); B via conflict-free LDS.
// ---------------------------------------------------------------------------
__global__ __launch_bounds__(256, 2) void gemm_tf32_kernel(
    const float* __restrict__ A,    // [M, 256]
    const float* __restrict__ Bw,   // [256, 640]
    const float* __restrict__ cj,   // [M]
    float* __restrict__ X,          // [M, 640]
    int M)
{
    constexpr int LDA = 20;    // BK(16) + 4 pad -> conflict-free LDSM
    constexpr int LDB = 136;   // BN(128) + 8 pad -> conflict-free B LDS
    __shared__ __align__(16) float As[2][128 * LDA];
    __shared__ __align__(16) float Bs[2][16 * LDB];

    const int t    = threadIdx.x;
    const int lane = t & 31;
    const int warp = t >> 5;
    const int wm   = (warp >> 2) * 64;     // 0 or 64
    const int wn   = (warp & 3) * 32;      // 0,32,64,96
    const int rowBase = blockIdx.y * 128;
    const int colBase = blockIdx.x * 128;

    // Global load mapping (per 16-wide k stage):
    // A: 128x16 floats = 512 float4; thread t -> rows t/4 and t/4+64, kcols (t&3)*4
    const int aRow = t >> 2;               // 0..63
    const int aCol = (t & 3) << 2;         // 0,4,8,12
    // B: 16x128 floats = 512 float4; thread t -> k rows t/32 and t/32+8, ncols (t&31)*4
    const int bRow = t >> 5;               // 0..7
    const int bCol = (t & 31) << 2;        // 0..124

    const bool v0 = (rowBase + aRow)      < M;
    const bool v1 = (rowBase + aRow + 64) < M;
    const float* Aptr0 = A + (size_t)(rowBase + aRow) * KDIM + aCol;
    const float* Aptr1 = Aptr0 + (size_t)64 * KDIM;
    const float* Bptr0 = Bw + (size_t)bRow * NCOMB + colBase + bCol;
    const float* Bptr1 = Bptr0 + (size_t)8 * NCOMB;

    const float4 f4z = make_float4(0.f, 0.f, 0.f, 0.f);

    float acc[4][4][4];
#pragma unroll
    for (int mt = 0; mt < 4; ++mt)
#pragma unroll
        for (int nt = 0; nt < 4; ++nt)
#pragma unroll
            for (int c = 0; c < 4; ++c) acc[mt][nt][c] = 0.f;

    // ldmatrix per-lane row address components (fp32 indices inside As)
    const int aFragRow = wm + (lane & 15);
    const int aFragCol = ((lane >> 4) & 1) * 4;
    // B fragment per-lane base (fp32 index inside Bs): b0 = B[k=lane%4][n=lane/4]
    const int bFragK = lane & 3;
    const int bFragN = wn + (lane >> 2);

    float4 pa0, pa1, pb0, pb1;

    // ---- prologue: stage 0 ----
    pa0 = v0 ? *(const float4*)(Aptr0) : f4z;
    pa1 = v1 ? *(const float4*)(Aptr1) : f4z;
    pb0 = *(const float4*)(Bptr0);
    pb1 = *(const float4*)(Bptr1);
    {
        float* as = As[0]; float* bs = Bs[0];
        *(float4*)&as[aRow * LDA + aCol]        = tf32x4(pa0);
        *(float4*)&as[(aRow + 64) * LDA + aCol] = tf32x4(pa1);
        *(float4*)&bs[bRow * LDB + bCol]        = tf32x4(pb0);
        *(float4*)&bs[(bRow + 8) * LDB + bCol]  = tf32x4(pb1);
    }
    __syncthreads();

    for (int s = 0; s < 16; ++s) {
        const int nxt = s + 1;
        if (nxt < 16) {
            const int k0 = nxt * 16;
            pa0 = v0 ? *(const float4*)(Aptr0 + k0) : f4z;
            pa1 = v1 ? *(const float4*)(Aptr1 + k0) : f4z;
            pb0 = *(const float4*)(Bptr0 + (size_t)k0 * NCOMB);
            pb1 = *(const float4*)(Bptr1 + (size_t)k0 * NCOMB);
        }

        const int buf = s & 1;
        float* as = As[buf];
        float* bs = Bs[buf];
        const uint32_t asb = (uint32_t)__cvta_generic_to_shared(as);

#pragma unroll
        for (int ks = 0; ks < 2; ++ks) {
            const int kk = ks * 8;
            uint32_t af[4][4];
#pragma unroll
            for (int mt = 0; mt < 4; ++mt) {
                uint32_t addr = asb +
                    (uint32_t)(((aFragRow + mt * 16) * LDA + kk + aFragCol) * 4);
                asm volatile(
                    "ldmatrix.sync.aligned.m8n8.x4.shared.b16 {%0,%1,%2,%3}, [%4];"
                    : "=r"(af[mt][0]), "=r"(af[mt][1]),
                      "=r"(af[mt][2]), "=r"(af[mt][3])
                    : "r"(addr));
            }
            uint32_t bf[4][2];
#pragma unroll
            for (int nt = 0; nt < 4; ++nt) {
                bf[nt][0] = __float_as_uint(bs[(kk + bFragK) * LDB + bFragN + nt * 8]);
                bf[nt][1] = __float_as_uint(bs[(kk + 4 + bFragK) * LDB + bFragN + nt * 8]);
            }
#pragma unroll
            for (int mt = 0; mt < 4; ++mt)
#pragma unroll
                for (int nt = 0; nt < 4; ++nt) {
                    asm volatile(
                        "mma.sync.aligned.m16n8k8.row.col.f32.tf32.tf32.f32 "
                        "{%0,%1,%2,%3}, {%4,%5,%6,%7}, {%8,%9}, {%0,%1,%2,%3};"
                        : "+f"(acc[mt][nt][0]), "+f"(acc[mt][nt][1]),
                          "+f"(acc[mt][nt][2]), "+f"(acc[mt][nt][3])
                        : "r"(af[mt][0]), "r"(af[mt][1]),
                          "r"(af[mt][2]), "r"(af[mt][3]),
                          "r"(bf[nt][0]), "r"(bf[nt][1]));
                }
        }

        if (nxt < 16) {
            float* asn = As[nxt & 1]; float* bsn = Bs[nxt & 1];
            *(float4*)&asn[aRow * LDA + aCol]        = tf32x4(pa0);
            *(float4*)&asn[(aRow + 64) * LDA + aCol] = tf32x4(pa1);
            *(float4*)&bsn[bRow * LDB + bCol]        = tf32x4(pb0);
            *(float4*)&bsn[(bRow + 8) * LDB + bCol]  = tf32x4(pb1);
        }
        __syncthreads();
    }

    // ---- epilogue: scale by cj[row], store float2 pairs ----
#pragma unroll
    for (int mt = 0; mt < 4; ++mt) {
        const int r0 = rowBase + wm + mt * 16 + (lane >> 2);
        const int r1 = r0 + 8;
        const float c0s = (r0 < M) ? __ldg(cj + r0) : 0.f;
        const float c1s = (r1 < M) ? __ldg(cj + r1) : 0.f;
#pragma unroll
        for (int nt = 0; nt < 4; ++nt) {
            const int col = colBase + wn + nt * 8 + (lane & 3) * 2;
            if (r0 < M) {
                float2 o; o.x = acc[mt][nt][0] * c0s; o.y = acc[mt][nt][1] * c0s;
                *(float2*)&X[(size_t)r0 * NCOMB + col] = o;
            }
            if (r1 < M) {
                float2 o; o.x = acc[mt][nt][2] * c1s; o.y = acc[mt][nt][3] * c1s;
                *(float2*)&X[(size_t)r1 * NCOMB + col] = o;
            }
        }
    }
}

// ---------------------------------------------------------------------------
// Kernel 4: edge scatter. One warp per edge: gather 128-float message row,
// vector-reduce-add into destination accumulator row.
// ---------------------------------------------------------------------------
__global__ __launch_bounds__(256) void scatter_kernel(
    const float* __restrict__ X,      // [n_src, 640]
    const int* __restrict__ esrc,     // [R*E]
    const int* __restrict__ edst,     // [R*E]
    float* __restrict__ acc)          // [n_dst, 128]
{
    long long w = (long long)blockIdx.x * 8 + (threadIdx.x >> 5);
    if (w >= (long long)RREL * NE) return;
    int lane = threadIdx.x & 31;
    int r = (int)(w / NE);
    int src = esrc[w];
    int dst = edst[w];

    const float4* xp = (const float4*)(X + (size_t)src * NCOMB + (size_t)r * OUTD);
    float4 v = xp[lane];

    float* ap = acc + (size_t)dst * OUTD + lane * 4;
    asm volatile("red.global.add.v4.f32 [%0], {%1, %2, %3, %4};"
                 :: "l"(ap), "f"(v.x), "f"(v.y), "f"(v.z), "f"(v.w)
                 : "memory");
}

// ---------------------------------------------------------------------------
// Kernel 5: finalize  out[n, o] = acc[n, o] * ci[n] + b[o]
// ---------------------------------------------------------------------------
__global__ void finalize_kernel(const float* __restrict__ acc,
                                const float* __restrict__ ci,
                                const float* __restrict__ b,
                                float* __restrict__ out, int n)
{
    int idx = blockIdx.x * blockDim.x + threadIdx.x;
    if (idx >= n * OUTD) return;
    int row = idx >> 7;
    int o = idx & (OUTD - 1);
    out[idx] = acc[idx] * ci[row] + b[o];
}

// ---------------------------------------------------------------------------
// Host launcher
// ---------------------------------------------------------------------------
extern "C" void kernel_launch(void* const* d_in, const int* in_sizes, int n_in,
                              void* d_out, int out_size)
{
    const float* ufeat   = (const float*)d_in[0];
    const float* ifeat   = (const float*)d_in[1];
    const float* cj_user = (const float*)d_in[2];
    const float* ci_user = (const float*)d_in[3];
    const float* cj_item = (const float*)d_in[4];
    const float* ci_item = (const float*)d_in[5];
    const float* W_u     = (const float*)d_in[6];
    const float* W_i     = (const float*)d_in[7];
    const float* Wu_fc   = (const float*)d_in[8];
    const float* bu      = (const float*)d_in[9];
    const float* Wi_fc   = (const float*)d_in[10];
    const float* bi      = (const float*)d_in[11];
    const int*   edge_u  = (const int*)d_in[12];
    const int*   edge_i  = (const int*)d_in[13];
    float* out = (float*)d_out;

    float *xu, *xi, *accu, *acci, *wcu, *wci;
    cudaGetSymbolAddress((void**)&xu,   g_xu);
    cudaGetSymbolAddress((void**)&xi,   g_xi);
    cudaGetSymbolAddress((void**)&accu, g_accu);
    cudaGetSymbolAddress((void**)&acci, g_acci);
    cudaGetSymbolAddress((void**)&wcu,  g_wcu);
    cudaGetSymbolAddress((void**)&wci,  g_wci);

    // 1) Fold per-relation projection into FC slice.
    int ctotal = KDIM * NCOMB;
    combine_w_kernel<<<(ctotal + 255) / 256, 256>>>(W_u, Wi_fc, wcu);
    combine_w_kernel<<<(ctotal + 255) / 256, 256>>>(W_i, Wu_fc, wci);

    // 2) Zero accumulators.
    zero_kernel<<<((NU * OUTD / 4) + 255) / 256, 256>>>((float4*)accu, NU * OUTD / 4);
    zero_kernel<<<((NI * OUTD / 4) + 255) / 256, 256>>>((float4*)acci, NI * OUTD / 4);

    // 3) Fused message GEMMs on TF32 tensor cores (cj folded into epilogue).
    dim3 gu(NCOMB / 128, (NU + 127) / 128);
    gemm_tf32_kernel<<<gu, 256>>>(ufeat, wcu, cj_user, xu, NU);
    dim3 gi(NCOMB / 128, (NI + 127) / 128);
    gemm_tf32_kernel<<<gi, 256>>>(ifeat, wci, cj_item, xi, NI);

    // 4) Edge scatter, both directions.
    long long totw = (long long)RREL * NE;
    int sblocks = (int)((totw * 32 + 255) / 256);
    scatter_kernel<<<sblocks, 256>>>(xu, edge_u, edge_i, acci);  // user -> item
    scatter_kernel<<<sblocks, 256>>>(xi, edge_i, edge_u, accu);  // item -> user

    // 5) Finalize: destination ci scaling + bias. Output = [new_u | new_i].
    finalize_kernel<<<((NU * OUTD) + 255) / 256, 256>>>(accu, ci_user, bu, out, NU);
    finalize_kernel<<<((NI * OUTD) + 255) / 256, 256>>>(acci, ci_item, bi,
                                                        out + (size_t)NU * OUTD, NI);
}

// round 13
// speedup vs baseline: 2.4448x; 1.6490x over previous
#include <cuda_runtime.h>
#include <cstdint>
#include <cstddef>

// ---------------------------------------------------------------------------
// Problem constants (fixed shapes per reference)
// ---------------------------------------------------------------------------
#define NU    100000
#define NI    50000
#define KDIM  256
#define MSGD  128
#define OUTD  128
#define RREL  5
#define NE    1000000
#define NCOMB (RREL * OUTD)   // 640

#define CAP_I 64              // bucket capacity per (r, item) — mean deg 20
#define CAP_U 40              // bucket capacity per (r, user) — mean deg 10
#define MAXOVF (1 << 20)

// ---------------------------------------------------------------------------
// Static device scratch (no runtime allocation allowed)
// ---------------------------------------------------------------------------
static __device__ float g_xu[(size_t)RREL * NU * OUTD];   // messages, [R][NU][128]
static __device__ float g_xi[(size_t)RREL * NI * OUTD];   // messages, [R][NI][128]
static __device__ float g_accu[(size_t)NU * OUTD];
static __device__ float g_acci[(size_t)NI * OUTD];
static __device__ float g_wcu[KDIM * NCOMB];
static __device__ float g_wci[KDIM * NCOMB];

static __device__ int g_cnt_i[RREL * NI];                  // per-(r,item) in-degree
static __device__ int g_cnt_u[RREL * NU];                  // per-(r,user) in-degree
static __device__ int g_bkt_i[(size_t)RREL * NI * CAP_I];  // 64 MB
static __device__ int g_bkt_u[(size_t)RREL * NU * CAP_U];  // 80 MB
static __device__ int g_ovf_i[MAXOVF];
static __device__ int g_ovf_u[MAXOVF];
static __device__ int g_ovfcnt[2];

// ---------------------------------------------------------------------------
// Kernel 1: combine weights  Wc[k][r*128+o] = sum_m W[r,k,m] * Wfc[r*128+m, o]
// ---------------------------------------------------------------------------
__global__ void combine_w_kernel(const float* __restrict__ W,
                                 const float* __restrict__ Wfc,
                                 float* __restrict__ Wc)
{
    int idx = blockIdx.x * blockDim.x + threadIdx.x;
    if (idx >= KDIM * NCOMB) return;
    int k = idx / NCOMB;
    int c = idx - k * NCOMB;
    int r = c / OUTD;
    int o = c - r * OUTD;
    const float* wrow = W + ((size_t)r * KDIM + k) * MSGD;
    const float* fc   = Wfc + ((size_t)r * MSGD) * OUTD + o;
    float s = 0.f;
#pragma unroll 8
    for (int m = 0; m < MSGD; ++m)
        s += wrow[m] * fc[(size_t)m * OUTD];
    Wc[idx] = s;
}

// ---------------------------------------------------------------------------
// Zero helpers
// ---------------------------------------------------------------------------
__global__ void zero_kernel(float4* __restrict__ p, int n4)
{
    int i = blockIdx.x * blockDim.x + threadIdx.x;
    if (i < n4) p[i] = make_float4(0.f, 0.f, 0.f, 0.f);
}

__global__ void zero_int_kernel(int4* __restrict__ p, int n4)
{
    int i = blockIdx.x * blockDim.x + threadIdx.x;
    if (i < n4) p[i] = make_int4(0, 0, 0, 0);
}

__global__ void zero_ovf_kernel(int* p)
{
    if (threadIdx.x < 2) p[threadIdx.x] = 0;
}

// ---------------------------------------------------------------------------
// TF32 helpers
// ---------------------------------------------------------------------------
__device__ __forceinline__ float to_tf32(float x)
{
    uint32_t u;
    asm("cvt.rna.tf32.f32 %0, %1;" : "=r"(u) : "f"(x));
    return __uint_as_float(u);
}

__device__ __forceinline__ float4 tf32x4(float4 v)
{
    v.x = to_tf32(v.x); v.y = to_tf32(v.y);
    v.z = to_tf32(v.z); v.w = to_tf32(v.w);
    return v;
}

// ---------------------------------------------------------------------------
// Kernel 3: TF32 tensor-core GEMM.
// X layout: [R][M][128]; block column index == relation (BN = 128 = OUTD).
// ---------------------------------------------------------------------------
__global__ __launch_bounds__(256, 2) void gemm_tf32_kernel(
    const float* __restrict__ A,    // [M, 256]
    const float* __restrict__ Bw,   // [256, 640]
    const float* __restrict__ cj,   // [M]
    float* __restrict__ X,          // [R][M][128]
    int M)
{
    constexpr int LDA = 20;
    constexpr int LDB = 136;
    __shared__ __align__(16) float As[2][128 * LDA];
    __shared__ __align__(16) float Bs[2][16 * LDB];

    const int t    = threadIdx.x;
    const int lane = t & 31;
    const int warp = t >> 5;
    const int wm   = (warp >> 2) * 64;
    const int wn   = (warp & 3) * 32;
    const int rowBase = blockIdx.y * 128;
    const int colBase = blockIdx.x * 128;

    const int aRow = t >> 2;
    const int aCol = (t & 3) << 2;
    const int bRow = t >> 5;
    const int bCol = (t & 31) << 2;

    const bool v0 = (rowBase + aRow)      < M;
    const bool v1 = (rowBase + aRow + 64) < M;
    const float* Aptr0 = A + (size_t)(rowBase + aRow) * KDIM + aCol;
    const float* Aptr1 = Aptr0 + (size_t)64 * KDIM;
    const float* Bptr0 = Bw + (size_t)bRow * NCOMB + colBase + bCol;
    const float* Bptr1 = Bptr0 + (size_t)8 * NCOMB;

    const float4 f4z = make_float4(0.f, 0.f, 0.f, 0.f);

    float acc[4][4][4];
#pragma unroll
    for (int mt = 0; mt < 4; ++mt)
#pragma unroll
        for (int nt = 0; nt < 4; ++nt)
#pragma unroll
            for (int c = 0; c < 4; ++c) acc[mt][nt][c] = 0.f;

    const int aFragRow = wm + (lane & 15);
    const int aFragCol = ((lane >> 4) & 1) * 4;
    const int bFragK = lane & 3;
    const int bFragN = wn + (lane >> 2);

    float4 pa0, pa1, pb0, pb1;

    pa0 = v0 ? *(const float4*)(Aptr0) : f4z;
    pa1 = v1 ? *(const float4*)(Aptr1) : f4z;
    pb0 = *(const float4*)(Bptr0);
    pb1 = *(const float4*)(Bptr1);
    {
        float* as = As[0]; float* bs = Bs[0];
        *(float4*)&as[aRow * LDA + aCol]        = tf32x4(pa0);
        *(float4*)&as[(aRow + 64) * LDA + aCol] = tf32x4(pa1);
        *(float4*)&bs[bRow * LDB + bCol]        = tf32x4(pb0);
        *(float4*)&bs[(bRow + 8) * LDB + bCol]  = tf32x4(pb1);
    }
    __syncthreads();

    for (int s = 0; s < 16; ++s) {
        const int nxt = s + 1;
        if (nxt < 16) {
            const int k0 = nxt * 16;
            pa0 = v0 ? *(const float4*)(Aptr0 + k0) : f4z;
            pa1 = v1 ? *(const float4*)(Aptr1 + k0) : f4z;
            pb0 = *(const float4*)(Bptr0 + (size_t)k0 * NCOMB);
            pb1 = *(const float4*)(Bptr1 + (size_t)k0 * NCOMB);
        }

        const int buf = s & 1;
        float* bs = Bs[buf];
        const uint32_t asb = (uint32_t)__cvta_generic_to_shared(As[buf]);

#pragma unroll
        for (int ks = 0; ks < 2; ++ks) {
            const int kk = ks * 8;
            uint32_t af[4][4];
#pragma unroll
            for (int mt = 0; mt < 4; ++mt) {
                uint32_t addr = asb +
                    (uint32_t)(((aFragRow + mt * 16) * LDA + kk + aFragCol) * 4);
                asm volatile(
                    "ldmatrix.sync.aligned.m8n8.x4.shared.b16 {%0,%1,%2,%3}, [%4];"
                    : "=r"(af[mt][0]), "=r"(af[mt][1]),
                      "=r"(af[mt][2]), "=r"(af[mt][3])
                    : "r"(addr));
            }
            uint32_t bf[4][2];
#pragma unroll
            for (int nt = 0; nt < 4; ++nt) {
                bf[nt][0] = __float_as_uint(bs[(kk + bFragK) * LDB + bFragN + nt * 8]);
                bf[nt][1] = __float_as_uint(bs[(kk + 4 + bFragK) * LDB + bFragN + nt * 8]);
            }
#pragma unroll
            for (int mt = 0; mt < 4; ++mt)
#pragma unroll
                for (int nt = 0; nt < 4; ++nt) {
                    asm volatile(
                        "mma.sync.aligned.m16n8k8.row.col.f32.tf32.tf32.f32 "
                        "{%0,%1,%2,%3}, {%4,%5,%6,%7}, {%8,%9}, {%0,%1,%2,%3};"
                        : "+f"(acc[mt][nt][0]), "+f"(acc[mt][nt][1]),
                          "+f"(acc[mt][nt][2]), "+f"(acc[mt][nt][3])
                        : "r"(af[mt][0]), "r"(af[mt][1]),
                          "r"(af[mt][2]), "r"(af[mt][3]),
                          "r"(bf[nt][0]), "r"(bf[nt][1]));
                }
        }

        if (nxt < 16) {
            float* asn = As[nxt & 1]; float* bsn = Bs[nxt & 1];
            *(float4*)&asn[aRow * LDA + aCol]        = tf32x4(pa0);
            *(float4*)&asn[(aRow + 64) * LDA + aCol] = tf32x4(pa1);
            *(float4*)&bsn[bRow * LDB + bCol]        = tf32x4(pb0);
            *(float4*)&bsn[(bRow + 8) * LDB + bCol]  = tf32x4(pb1);
        }
        __syncthreads();
    }

    // Epilogue: X[r][row][col] = acc * cj[row]; r == blockIdx.x
    float* Xr = X + (size_t)blockIdx.x * M * OUTD;
#pragma unroll
    for (int mt = 0; mt < 4; ++mt) {
        const int r0 = rowBase + wm + mt * 16 + (lane >> 2);
        const int r1 = r0 + 8;
        const float c0s = (r0 < M) ? __ldg(cj + r0) : 0.f;
        const float c1s = (r1 < M) ? __ldg(cj + r1) : 0.f;
#pragma unroll
        for (int nt = 0; nt < 4; ++nt) {
            const int col = wn + nt * 8 + (lane & 3) * 2;
            if (r0 < M) {
                float2 o; o.x = acc[mt][nt][0] * c0s; o.y = acc[mt][nt][1] * c0s;
                *(float2*)&Xr[(size_t)r0 * OUTD + col] = o;
            }
            if (r1 < M) {
                float2 o; o.x = acc[mt][nt][2] * c1s; o.y = acc[mt][nt][3] * c1s;
                *(float2*)&Xr[(size_t)r1 * OUTD + col] = o;
            }
        }
    }
}

// ---------------------------------------------------------------------------
// Kernel 4a: bin edges by (relation, dst) into fixed-capacity buckets.
// ---------------------------------------------------------------------------
template <int N, int CAP>
__global__ __launch_bounds__(256) void bin_kernel(
    const int* __restrict__ dstArr,   // [R*E]
    const int* __restrict__ srcArr,   // [R*E]
    int* __restrict__ cnt,            // [R*N]
    int* __restrict__ bkt,            // [R*N*CAP]
    int* __restrict__ ovf,
    int* __restrict__ ovfcnt)
{
    int w = blockIdx.x * 256 + threadIdx.x;
    if (w >= RREL * NE) return;
    int r = w / NE;
    int key = r * N + dstArr[w];
    int pos = atomicAdd(&cnt[key], 1);
    if (pos < CAP) {
        bkt[(size_t)key * CAP + pos] = srcArr[w];
    } else {
        int o = atomicAdd(ovfcnt, 1);
        if (o < MAXOVF) ovf[o] = w;
    }
}

// ---------------------------------------------------------------------------
// Kernel 4b: gather-aggregate. One warp per (relation, dst) segment:
// register-accumulate the segment's message rows, ONE red.v4 per segment.
// ---------------------------------------------------------------------------
template <int N, int CAP, int MSRC>
__global__ __launch_bounds__(256) void gather_kernel(
    const float* __restrict__ X,      // [R][MSRC][128]
    const int* __restrict__ cnt,      // [R*N]
    const int* __restrict__ bkt,      // [R*N*CAP]
    float* __restrict__ acc)          // [N, 128]
{
    int key = blockIdx.x * 8 + (threadIdx.x >> 5);
    if (key >= RREL * N) return;
    int lane = threadIdx.x & 31;
    int n = cnt[key];
    if (n == 0) return;
    int m = n < CAP ? n : CAP;
    int r = key / N;
    int dst = key - r * N;
    const int* b = bkt + (size_t)key * CAP;
    const float* Xr = X + (size_t)r * MSRC * OUTD + (size_t)lane * 4;

    float4 s = make_float4(0.f, 0.f, 0.f, 0.f);
#pragma unroll 4
    for (int i = 0; i < m; ++i) {
        int src = b[i];
        float4 v = *(const float4*)(Xr + (size_t)src * OUTD);
        s.x += v.x; s.y += v.y; s.z += v.z; s.w += v.w;
    }

    float* ap = acc + (size_t)dst * OUTD + lane * 4;
    asm volatile("red.global.add.v4.f32 [%0], {%1, %2, %3, %4};"
                 :: "l"(ap), "f"(s.x), "f"(s.y), "f"(s.z), "f"(s.w)
                 : "memory");
}

// ---------------------------------------------------------------------------
// Kernel 4c: overflow fallback (expected empty; kept for correctness).
// ---------------------------------------------------------------------------
template <int MSRC>
__global__ __launch_bounds__(256) void ovf_kernel(
    const float* __restrict__ X,
    const int* __restrict__ srcArr,
    const int* __restrict__ dstArr,
    const int* __restrict__ ovf,
    const int* __restrict__ ovfcnt,
    float* __restrict__ acc)
{
    int nov = *ovfcnt;
    if (nov > MAXOVF) nov = MAXOVF;
    int lane = threadIdx.x & 31;
    for (int idx = blockIdx.x * 8 + (threadIdx.x >> 5); idx < nov;
         idx += gridDim.x * 8) {
        int w = ovf[idx];
        int r = w / NE;
        int src = srcArr[w];
        int dst = dstArr[w];
        float4 v = *(const float4*)(X + ((size_t)r * MSRC + src) * OUTD + lane * 4);
        float* ap = acc + (size_t)dst * OUTD + lane * 4;
        asm volatile("red.global.add.v4.f32 [%0], {%1, %2, %3, %4};"
                     :: "l"(ap), "f"(v.x), "f"(v.y), "f"(v.z), "f"(v.w)
                     : "memory");
    }
}

// ---------------------------------------------------------------------------
// Kernel 5: finalize  out[n, o] = acc[n, o] * ci[n] + b[o]
// ---------------------------------------------------------------------------
__global__ void finalize_kernel(const float* __restrict__ acc,
                                const float* __restrict__ ci,
                                const float* __restrict__ b,
                                float* __restrict__ out, int n)
{
    int idx = blockIdx.x * blockDim.x + threadIdx.x;
    if (idx >= n * OUTD) return;
    int row = idx >> 7;
    int o = idx & (OUTD - 1);
    out[idx] = acc[idx] * ci[row] + b[o];
}

// ---------------------------------------------------------------------------
// Host launcher
// ---------------------------------------------------------------------------
extern "C" void kernel_launch(void* const* d_in, const int* in_sizes, int n_in,
                              void* d_out, int out_size)
{
    const float* ufeat   = (const float*)d_in[0];
    const float* ifeat   = (const float*)d_in[1];
    const float* cj_user = (const float*)d_in[2];
    const float* ci_user = (const float*)d_in[3];
    const float* cj_item = (const float*)d_in[4];
    const float* ci_item = (const float*)d_in[5];
    const float* W_u     = (const float*)d_in[6];
    const float* W_i     = (const float*)d_in[7];
    const float* Wu_fc   = (const float*)d_in[8];
    const float* bu      = (const float*)d_in[9];
    const float* Wi_fc   = (const float*)d_in[10];
    const float* bi      = (const float*)d_in[11];
    const int*   edge_u  = (const int*)d_in[12];
    const int*   edge_i  = (const int*)d_in[13];
    float* out = (float*)d_out;

    float *xu, *xi, *accu, *acci, *wcu, *wci;
    int *cnt_i, *cnt_u, *bkt_i, *bkt_u, *ovf_i, *ovf_u, *ovfc;
    cudaGetSymbolAddress((void**)&xu,    g_xu);
    cudaGetSymbolAddress((void**)&xi,    g_xi);
    cudaGetSymbolAddress((void**)&accu,  g_accu);
    cudaGetSymbolAddress((void**)&acci,  g_acci);
    cudaGetSymbolAddress((void**)&wcu,   g_wcu);
    cudaGetSymbolAddress((void**)&wci,   g_wci);
    cudaGetSymbolAddress((void**)&cnt_i, g_cnt_i);
    cudaGetSymbolAddress((void**)&cnt_u, g_cnt_u);
    cudaGetSymbolAddress((void**)&bkt_i, g_bkt_i);
    cudaGetSymbolAddress((void**)&bkt_u, g_bkt_u);
    cudaGetSymbolAddress((void**)&ovf_i, g_ovf_i);
    cudaGetSymbolAddress((void**)&ovf_u, g_ovf_u);
    cudaGetSymbolAddress((void**)&ovfc,  g_ovfcnt);

    // 1) Fold per-relation projection into FC slice.
    int ctotal = KDIM * NCOMB;
    combine_w_kernel<<<(ctotal + 255) / 256, 256>>>(W_u, Wi_fc, wcu);
    combine_w_kernel<<<(ctotal + 255) / 256, 256>>>(W_i, Wu_fc, wci);

    // 2) Zero accumulators, degree counters, overflow counters.
    zero_kernel<<<((NU * OUTD / 4) + 255) / 256, 256>>>((float4*)accu, NU * OUTD / 4);
    zero_kernel<<<((NI * OUTD / 4) + 255) / 256, 256>>>((float4*)acci, NI * OUTD / 4);
    zero_int_kernel<<<((RREL * NI / 4) + 255) / 256, 256>>>((int4*)cnt_i, RREL * NI / 4);
    zero_int_kernel<<<((RREL * NU / 4) + 255) / 256, 256>>>((int4*)cnt_u, RREL * NU / 4);
    zero_ovf_kernel<<<1, 32>>>(ovfc);

    // 3) Bin edges by (relation, dst).
    int bblocks = (RREL * NE + 255) / 256;
    bin_kernel<NI, CAP_I><<<bblocks, 256>>>(edge_i, edge_u, cnt_i, bkt_i, ovf_i, ovfc + 0);
    bin_kernel<NU, CAP_U><<<bblocks, 256>>>(edge_u, edge_i, cnt_u, bkt_u, ovf_u, ovfc + 1);

    // 4) Fused message GEMMs on TF32 tensor cores ([R][M][128] layout).
    dim3 gu(NCOMB / 128, (NU + 127) / 128);
    gemm_tf32_kernel<<<gu, 256>>>(ufeat, wcu, cj_user, xu, NU);
    dim3 gi(NCOMB / 128, (NI + 127) / 128);
    gemm_tf32_kernel<<<gi, 256>>>(ifeat, wci, cj_item, xi, NI);

    // 5) Gather-aggregate per (relation, dst): one red.v4 per segment.
    gather_kernel<NI, CAP_I, NU><<<(RREL * NI + 7) / 8, 256>>>(xu, cnt_i, bkt_i, acci);
    gather_kernel<NU, CAP_U, NI><<<(RREL * NU + 7) / 8, 256>>>(xi, cnt_u, bkt_u, accu);

    // 6) Overflow fallback (normally zero work).
    ovf_kernel<NU><<<256, 256>>>(xu, edge_u, edge_i, ovf_i, ovfc + 0, acci);
    ovf_kernel<NI><<<256, 256>>>(xi, edge_i, edge_u, ovf_u, ovfc + 1, accu);

    // 7) Finalize: destination ci scaling + bias. Output = [new_u | new_i].
    finalize_kernel<<<((NU * OUTD) + 255) / 256, 256>>>(accu, ci_user, bu, out, NU);
    finalize_kernel<<<((NI * OUTD) + 255) / 256, 256>>>(acci, ci_item, bi,
                                                        out + (size_t)NU * OUTD, NI);
}

// round 14
// speedup vs baseline: 2.8462x; 1.1642x over previous
#include <cuda_runtime.h>
#include <cuda_fp16.h>
#include <cstdint>
#include <cstddef>

// ---------------------------------------------------------------------------
// Problem constants (fixed shapes per reference)
// ---------------------------------------------------------------------------
#define NU    100000
#define NI    50000
#define KDIM  256
#define MSGD  128
#define OUTD  128
#define RREL  5
#define NE    1000000
#define NCOMB (RREL * OUTD)   // 640

#define CAP_I 64              // bucket capacity per (r, item) — mean deg 20
#define CAP_U 40              // bucket capacity per (r, user) — mean deg 10
#define MAXOVF (1 << 20)

// ---------------------------------------------------------------------------
// Static device scratch (no runtime allocation allowed)
// ---------------------------------------------------------------------------
static __device__ float g_xu[(size_t)RREL * NU * OUTD];   // messages, [R][NU][128]
static __device__ float g_xi[(size_t)RREL * NI * OUTD];   // messages, [R][NI][128]
static __device__ float g_accu[(size_t)NU * OUTD];
static __device__ float g_acci[(size_t)NI * OUTD];
static __device__ float g_wcu[KDIM * NCOMB];
static __device__ float g_wci[KDIM * NCOMB];

static __device__ int g_cnt_i[RREL * NI];
static __device__ int g_cnt_u[RREL * NU];
static __device__ int g_bkt_i[(size_t)RREL * NI * CAP_I];
static __device__ int g_bkt_u[(size_t)RREL * NU * CAP_U];
static __device__ int g_ovf_i[MAXOVF];
static __device__ int g_ovf_u[MAXOVF];
static __device__ int g_ovfcnt[2];

// ---------------------------------------------------------------------------
// Kernel 1: combine weights  Wc[k][r*128+o] = sum_m W[r,k,m] * Wfc[r*128+m, o]
// ---------------------------------------------------------------------------
__global__ void combine_w_kernel(const float* __restrict__ W,
                                 const float* __restrict__ Wfc,
                                 float* __restrict__ Wc)
{
    int idx = blockIdx.x * blockDim.x + threadIdx.x;
    if (idx >= KDIM * NCOMB) return;
    int k = idx / NCOMB;
    int c = idx - k * NCOMB;
    int r = c / OUTD;
    int o = c - r * OUTD;
    const float* wrow = W + ((size_t)r * KDIM + k) * MSGD;
    const float* fc   = Wfc + ((size_t)r * MSGD) * OUTD + o;
    float s = 0.f;
#pragma unroll 8
    for (int m = 0; m < MSGD; ++m)
        s += wrow[m] * fc[(size_t)m * OUTD];
    Wc[idx] = s;
}

// ---------------------------------------------------------------------------
// Zero helpers
// ---------------------------------------------------------------------------
__global__ void zero_kernel(float4* __restrict__ p, int n4)
{
    int i = blockIdx.x * blockDim.x + threadIdx.x;
    if (i < n4) p[i] = make_float4(0.f, 0.f, 0.f, 0.f);
}

__global__ void zero_int_kernel(int4* __restrict__ p, int n4)
{
    int i = blockIdx.x * blockDim.x + threadIdx.x;
    if (i < n4) p[i] = make_int4(0, 0, 0, 0);
}

__global__ void zero_ovf_kernel(int* p)
{
    if (threadIdx.x < 2) p[threadIdx.x] = 0;
}

// ---------------------------------------------------------------------------
// fp16 helpers: pack float4 -> 4 halfs (uint2)
// ---------------------------------------------------------------------------
__device__ __forceinline__ uint2 f4_to_h4(float4 v)
{
    __half2 lo = __float22half2_rn(make_float2(v.x, v.y));
    __half2 hi = __float22half2_rn(make_float2(v.z, v.w));
    uint2 r;
    r.x = *(uint32_t*)&lo;
    r.y = *(uint32_t*)&hi;
    return r;
}

// ---------------------------------------------------------------------------
// Kernel 3: FP16 tensor-core GEMM (fp32 accumulate).
// X layout: [R][M][128]; block column index == relation (BN = 128 = OUTD).
// Block tile 128x128, BK=16, double-buffered fp16 smem.
// 8 warps 2x4 -> warp tile 64x32 = 4x4 m16n8k16 mma tiles.
// A frags: ldmatrix.x4 ; B frags: ldmatrix.x4.trans (2 per warp per stage).
// ---------------------------------------------------------------------------
__global__ __launch_bounds__(256, 2) void gemm_f16_kernel(
    const float* __restrict__ A,    // [M, 256] fp32
    const float* __restrict__ Bw,   // [256, 640] fp32
    const float* __restrict__ cj,   // [M]
    float* __restrict__ X,          // [R][M][128]
    int M)
{
    constexpr int LDA = 24;    // halfs per A row (16 + 8 pad) -> ldmatrix stride 48B
    constexpr int LDB = 136;   // halfs per B row (128 + 8 pad) -> trans stride 272B
    __shared__ __align__(16) __half As[2][128 * LDA];
    __shared__ __align__(16) __half Bs[2][16 * LDB];

    const int t    = threadIdx.x;
    const int lane = t & 31;
    const int warp = t >> 5;
    const int wm   = (warp >> 2) * 64;     // 0 or 64
    const int wn   = (warp & 3) * 32;      // 0,32,64,96
    const int rowBase = blockIdx.y * 128;

    // Global load mapping (per 16-wide k stage):
    const int aRow = t >> 2;               // 0..63 (plus +64 second half)
    const int aCol = (t & 3) << 2;         // k offset 0,4,8,12
    const int bRow = t >> 5;               // 0..7 (plus +8)
    const int bCol = (t & 31) << 2;        // n offset 0..124

    const bool v0 = (rowBase + aRow)      < M;
    const bool v1 = (rowBase + aRow + 64) < M;
    const float* Aptr0 = A + (size_t)(rowBase + aRow) * KDIM + aCol;
    const float* Aptr1 = Aptr0 + (size_t)64 * KDIM;
    const float* Bptr0 = Bw + (size_t)bRow * NCOMB + blockIdx.x * 128 + bCol;
    const float* Bptr1 = Bptr0 + (size_t)8 * NCOMB;

    const float4 f4z = make_float4(0.f, 0.f, 0.f, 0.f);

    float acc[4][4][4];
#pragma unroll
    for (int mt = 0; mt < 4; ++mt)
#pragma unroll
        for (int nt = 0; nt < 4; ++nt)
#pragma unroll
            for (int c = 0; c < 4; ++c) acc[mt][nt][c] = 0.f;

    // ldmatrix per-lane addressing (in halfs):
    // A (x4, non-trans): lanes 0-15 -> rows m0-15 @ k0 ; lanes 16-31 -> m0-15 @ k8
    const int aLdRow = wm + (lane & 15);
    const int aLdK   = ((lane >> 4) & 1) * 8;
    // B (x4, trans): lanes -> row k = lane&15, col n + ((lane>=16)?8:0)
    const int bLdK = lane & 15;
    const int bLdN = ((lane >> 4) & 1) * 8;

    float4 pa0, pa1, pb0, pb1;

    // ---- prologue: stage 0 ----
    pa0 = v0 ? *(const float4*)(Aptr0) : f4z;
    pa1 = v1 ? *(const float4*)(Aptr1) : f4z;
    pb0 = *(const float4*)(Bptr0);
    pb1 = *(const float4*)(Bptr1);
    {
        __half* as = As[0]; __half* bs = Bs[0];
        *(uint2*)&as[aRow * LDA + aCol]        = f4_to_h4(pa0);
        *(uint2*)&as[(aRow + 64) * LDA + aCol] = f4_to_h4(pa1);
        *(uint2*)&bs[bRow * LDB + bCol]        = f4_to_h4(pb0);
        *(uint2*)&bs[(bRow + 8) * LDB + bCol]  = f4_to_h4(pb1);
    }
    __syncthreads();

    for (int s = 0; s < 16; ++s) {
        const int nxt = s + 1;
        if (nxt < 16) {
            const int k0 = nxt * 16;
            pa0 = v0 ? *(const float4*)(Aptr0 + k0) : f4z;
            pa1 = v1 ? *(const float4*)(Aptr1 + k0) : f4z;
            pb0 = *(const float4*)(Bptr0 + (size_t)k0 * NCOMB);
            pb1 = *(const float4*)(Bptr1 + (size_t)k0 * NCOMB);
        }

        const int buf = s & 1;
        const uint32_t asb = (uint32_t)__cvta_generic_to_shared(As[buf]);
        const uint32_t bsb = (uint32_t)__cvta_generic_to_shared(Bs[buf]);

        // A fragments: one ldmatrix.x4 per mt (m16 x k16)
        uint32_t af[4][4];
#pragma unroll
        for (int mt = 0; mt < 4; ++mt) {
            uint32_t addr = asb +
                (uint32_t)(((aLdRow + mt * 16) * LDA + aLdK) * 2);
            asm volatile(
                "ldmatrix.sync.aligned.m8n8.x4.shared.b16 {%0,%1,%2,%3}, [%4];"
                : "=r"(af[mt][0]), "=r"(af[mt][1]),
                  "=r"(af[mt][2]), "=r"(af[mt][3])
                : "r"(addr));
        }
        // B fragments: ldmatrix.x4.trans per nt-pair (k16 x n16)
        uint32_t bf[4][2];
#pragma unroll
        for (int np = 0; np < 2; ++np) {
            uint32_t addr = bsb +
                (uint32_t)((bLdK * LDB + wn + np * 16 + bLdN) * 2);
            uint32_t r0, r1, r2, r3;
            asm volatile(
                "ldmatrix.sync.aligned.m8n8.x4.trans.shared.b16 {%0,%1,%2,%3}, [%4];"
                : "=r"(r0), "=r"(r1), "=r"(r2), "=r"(r3)
                : "r"(addr));
            bf[np * 2 + 0][0] = r0; bf[np * 2 + 0][1] = r1;
            bf[np * 2 + 1][0] = r2; bf[np * 2 + 1][1] = r3;
        }

#pragma unroll
        for (int mt = 0; mt < 4; ++mt)
#pragma unroll
            for (int nt = 0; nt < 4; ++nt) {
                asm volatile(
                    "mma.sync.aligned.m16n8k16.row.col.f32.f16.f16.f32 "
                    "{%0,%1,%2,%3}, {%4,%5,%6,%7}, {%8,%9}, {%0,%1,%2,%3};"
                    : "+f"(acc[mt][nt][0]), "+f"(acc[mt][nt][1]),
                      "+f"(acc[mt][nt][2]), "+f"(acc[mt][nt][3])
                    : "r"(af[mt][0]), "r"(af[mt][1]),
                      "r"(af[mt][2]), "r"(af[mt][3]),
                      "r"(bf[nt][0]), "r"(bf[nt][1]));
            }

        if (nxt < 16) {
            __half* asn = As[nxt & 1]; __half* bsn = Bs[nxt & 1];
            *(uint2*)&asn[aRow * LDA + aCol]        = f4_to_h4(pa0);
            *(uint2*)&asn[(aRow + 64) * LDA + aCol] = f4_to_h4(pa1);
            *(uint2*)&bsn[bRow * LDB + bCol]        = f4_to_h4(pb0);
            *(uint2*)&bsn[(bRow + 8) * LDB + bCol]  = f4_to_h4(pb1);
        }
        __syncthreads();
    }

    // Epilogue: X[r][row][col] = acc * cj[row]; r == blockIdx.x
    float* Xr = X + (size_t)blockIdx.x * M * OUTD;
#pragma unroll
    for (int mt = 0; mt < 4; ++mt) {
        const int r0 = rowBase + wm + mt * 16 + (lane >> 2);
        const int r1 = r0 + 8;
        const float c0s = (r0 < M) ? __ldg(cj + r0) : 0.f;
        const float c1s = (r1 < M) ? __ldg(cj + r1) : 0.f;
#pragma unroll
        for (int nt = 0; nt < 4; ++nt) {
            const int col = wn + nt * 8 + (lane & 3) * 2;
            if (r0 < M) {
                float2 o; o.x = acc[mt][nt][0] * c0s; o.y = acc[mt][nt][1] * c0s;
                *(float2*)&Xr[(size_t)r0 * OUTD + col] = o;
            }
            if (r1 < M) {
                float2 o; o.x = acc[mt][nt][2] * c1s; o.y = acc[mt][nt][3] * c1s;
                *(float2*)&Xr[(size_t)r1 * OUTD + col] = o;
            }
        }
    }
}

// ---------------------------------------------------------------------------
// Kernel 4a: bin edges by (relation, dst) into fixed-capacity buckets.
// ---------------------------------------------------------------------------
template <int N, int CAP>
__global__ __launch_bounds__(256) void bin_kernel(
    const int* __restrict__ dstArr,   // [R*E]
    const int* __restrict__ srcArr,   // [R*E]
    int* __restrict__ cnt,            // [R*N]
    int* __restrict__ bkt,            // [R*N*CAP]
    int* __restrict__ ovf,
    int* __restrict__ ovfcnt)
{
    int w = blockIdx.x * 256 + threadIdx.x;
    if (w >= RREL * NE) return;
    int r = w / NE;
    int key = r * N + dstArr[w];
    int pos = atomicAdd(&cnt[key], 1);
    if (pos < CAP) {
        bkt[(size_t)key * CAP + pos] = srcArr[w];
    } else {
        int o = atomicAdd(ovfcnt, 1);
        if (o < MAXOVF) ovf[o] = w;
    }
}

// ---------------------------------------------------------------------------
// Kernel 4b: gather-aggregate. One warp per (relation, dst) segment.
// ---------------------------------------------------------------------------
template <int N, int CAP, int MSRC>
__global__ __launch_bounds__(256) void gather_kernel(
    const float* __restrict__ X,      // [R][MSRC][128]
    const int* __restrict__ cnt,      // [R*N]
    const int* __restrict__ bkt,      // [R*N*CAP]
    float* __restrict__ acc)          // [N, 128]
{
    int key = blockIdx.x * 8 + (threadIdx.x >> 5);
    if (key >= RREL * N) return;
    int lane = threadIdx.x & 31;
    int n = cnt[key];
    if (n == 0) return;
    int m = n < CAP ? n : CAP;
    int r = key / N;
    int dst = key - r * N;
    const int* b = bkt + (size_t)key * CAP;
    const float* Xr = X + (size_t)r * MSRC * OUTD + (size_t)lane * 4;

    float4 s = make_float4(0.f, 0.f, 0.f, 0.f);
#pragma unroll 4
    for (int i = 0; i < m; ++i) {
        int src = b[i];
        float4 v = *(const float4*)(Xr + (size_t)src * OUTD);
        s.x += v.x; s.y += v.y; s.z += v.z; s.w += v.w;
    }

    float* ap = acc + (size_t)dst * OUTD + lane * 4;
    asm volatile("red.global.add.v4.f32 [%0], {%1, %2, %3, %4};"
                 :: "l"(ap), "f"(s.x), "f"(s.y), "f"(s.z), "f"(s.w)
                 : "memory");
}

// ---------------------------------------------------------------------------
// Kernel 4c: overflow fallback (expected empty; kept for correctness).
// ---------------------------------------------------------------------------
template <int MSRC>
__global__ __launch_bounds__(256) void ovf_kernel(
    const float* __restrict__ X,
    const int* __restrict__ srcArr,
    const int* __restrict__ dstArr,
    const int* __restrict__ ovf,
    const int* __restrict__ ovfcnt,
    float* __restrict__ acc)
{
    int nov = *ovfcnt;
    if (nov > MAXOVF) nov = MAXOVF;
    int lane = threadIdx.x & 31;
    for (int idx = blockIdx.x * 8 + (threadIdx.x >> 5); idx < nov;
         idx += gridDim.x * 8) {
        int w = ovf[idx];
        int r = w / NE;
        int src = srcArr[w];
        int dst = dstArr[w];
        float4 v = *(const float4*)(X + ((size_t)r * MSRC + src) * OUTD + lane * 4);
        float* ap = acc + (size_t)dst * OUTD + lane * 4;
        asm volatile("red.global.add.v4.f32 [%0], {%1, %2, %3, %4};"
                     :: "l"(ap), "f"(v.x), "f"(v.y), "f"(v.z), "f"(v.w)
                     : "memory");
    }
}

// ---------------------------------------------------------------------------
// Kernel 5: finalize  out[n, o] = acc[n, o] * ci[n] + b[o]   (float4 lanes)
// ---------------------------------------------------------------------------
__global__ void finalize_kernel(const float4* __restrict__ acc,
                                const float* __restrict__ ci,
                                const float4* __restrict__ b,
                                float4* __restrict__ out, int n4)
{
    int idx = blockIdx.x * blockDim.x + threadIdx.x;
    if (idx >= n4) return;
    int row = idx >> 5;                 // 32 float4 per row
    int o4  = idx & 31;
    float c = ci[row];
    float4 a = acc[idx];
    float4 bb = b[o4];
    float4 r;
    r.x = a.x * c + bb.x; r.y = a.y * c + bb.y;
    r.z = a.z * c + bb.z; r.w = a.w * c + bb.w;
    out[idx] = r;
}

// ---------------------------------------------------------------------------
// Host launcher
// ---------------------------------------------------------------------------
extern "C" void kernel_launch(void* const* d_in, const int* in_sizes, int n_in,
                              void* d_out, int out_size)
{
    const float* ufeat   = (const float*)d_in[0];
    const float* ifeat   = (const float*)d_in[1];
    const float* cj_user = (const float*)d_in[2];
    const float* ci_user = (const float*)d_in[3];
    const float* cj_item = (const float*)d_in[4];
    const float* ci_item = (const float*)d_in[5];
    const float* W_u     = (const float*)d_in[6];
    const float* W_i     = (const float*)d_in[7];
    const float* Wu_fc   = (const float*)d_in[8];
    const float* bu      = (const float*)d_in[9];
    const float* Wi_fc   = (const float*)d_in[10];
    const float* bi      = (const float*)d_in[11];
    const int*   edge_u  = (const int*)d_in[12];
    const int*   edge_i  = (const int*)d_in[13];
    float* out = (float*)d_out;

    float *xu, *xi, *accu, *acci, *wcu, *wci;
    int *cnt_i, *cnt_u, *bkt_i, *bkt_u, *ovf_i, *ovf_u, *ovfc;
    cudaGetSymbolAddress((void**)&xu,    g_xu);
    cudaGetSymbolAddress((void**)&xi,    g_xi);
    cudaGetSymbolAddress((void**)&accu,  g_accu);
    cudaGetSymbolAddress((void**)&acci,  g_acci);
    cudaGetSymbolAddress((void**)&wcu,   g_wcu);
    cudaGetSymbolAddress((void**)&wci,   g_wci);
    cudaGetSymbolAddress((void**)&cnt_i, g_cnt_i);
    cudaGetSymbolAddress((void**)&cnt_u, g_cnt_u);
    cudaGetSymbolAddress((void**)&bkt_i, g_bkt_i);
    cudaGetSymbolAddress((void**)&bkt_u, g_bkt_u);
    cudaGetSymbolAddress((void**)&ovf_i, g_ovf_i);
    cudaGetSymbolAddress((void**)&ovf_u, g_ovf_u);
    cudaGetSymbolAddress((void**)&ovfc,  g_ovfcnt);

    // 1) Fold per-relation projection into FC slice.
    int ctotal = KDIM * NCOMB;
    combine_w_kernel<<<(ctotal + 255) / 256, 256>>>(W_u, Wi_fc, wcu);
    combine_w_kernel<<<(ctotal + 255) / 256, 256>>>(W_i, Wu_fc, wci);

    // 2) Zero accumulators, degree counters, overflow counters.
    zero_kernel<<<((NU * OUTD / 4) + 255) / 256, 256>>>((float4*)accu, NU * OUTD / 4);
    zero_kernel<<<((NI * OUTD / 4) + 255) / 256, 256>>>((float4*)acci, NI * OUTD / 4);
    zero_int_kernel<<<((RREL * NI / 4) + 255) / 256, 256>>>((int4*)cnt_i, RREL * NI / 4);
    zero_int_kernel<<<((RREL * NU / 4) + 255) / 256, 256>>>((int4*)cnt_u, RREL * NU / 4);
    zero_ovf_kernel<<<1, 32>>>(ovfc);

    // 3) Bin edges by (relation, dst).
    int bblocks = (RREL * NE + 255) / 256;
    bin_kernel<NI, CAP_I><<<bblocks, 256>>>(edge_i, edge_u, cnt_i, bkt_i, ovf_i, ovfc + 0);
    bin_kernel<NU, CAP_U><<<bblocks, 256>>>(edge_u, edge_i, cnt_u, bkt_u, ovf_u, ovfc + 1);

    // 4) Fused message GEMMs on FP16 tensor cores ([R][M][128] layout).
    dim3 gu(NCOMB / 128, (NU + 127) / 128);
    gemm_f16_kernel<<<gu, 256>>>(ufeat, wcu, cj_user, xu, NU);
    dim3 gi(NCOMB / 128, (NI + 127) / 128);
    gemm_f16_kernel<<<gi, 256>>>(ifeat, wci, cj_item, xi, NI);

    // 5) Gather-aggregate per (relation, dst): one red.v4 per segment.
    gather_kernel<NI, CAP_I, NU><<<(RREL * NI + 7) / 8, 256>>>(xu, cnt_i, bkt_i, acci);
    gather_kernel<NU, CAP_U, NI><<<(RREL * NU + 7) / 8, 256>>>(xi, cnt_u, bkt_u, accu);

    // 6) Overflow fallback (normally zero work).
    ovf_kernel<NU><<<256, 256>>>(xu, edge_u, edge_i, ovf_i, ovfc + 0, acci);
    ovf_kernel<NI><<<256, 256>>>(xi, edge_i, edge_u, ovf_u, ovfc + 1, accu);

    // 7) Finalize: destination ci scaling + bias. Output = [new_u | new_i].
    finalize_kernel<<<((NU * OUTD / 4) + 255) / 256, 256>>>(
        (const float4*)accu, ci_user, (const float4*)bu, (float4*)out, NU * OUTD / 4);
    finalize_kernel<<<((NI * OUTD / 4) + 255) / 256, 256>>>(
        (const float4*)acci, ci_item, (const float4*)bi,
        (float4*)(out + (size_t)NU * OUTD), NI * OUTD / 4);
}

// round 15
// speedup vs baseline: 3.2854x; 1.1543x over previous
#include <cuda_runtime.h>
#include <cuda_fp16.h>
#include <cstdint>
#include <cstddef>

// ---------------------------------------------------------------------------
// Problem constants (fixed shapes per reference)
// ---------------------------------------------------------------------------
#define NU    100000
#define NI    50000
#define KDIM  256
#define MSGD  128
#define OUTD  128
#define RREL  5
#define NE    1000000
#define NCOMB (RREL * OUTD)   // 640

#define CAP_I 64              // bucket capacity per (r, item) — mean deg 20
#define CAP_U 40              // bucket capacity per (r, user) — mean deg 10
#define MAXOVF (1 << 20)

// ---------------------------------------------------------------------------
// Static device scratch (no runtime allocation allowed)
// ---------------------------------------------------------------------------
static __device__ __half g_xu[(size_t)RREL * NU * OUTD];  // messages fp16, [R][NU][128]
static __device__ __half g_xi[(size_t)RREL * NI * OUTD];  // messages fp16, [R][NI][128]
static __device__ float g_wcu[KDIM * NCOMB];
static __device__ float g_wci[KDIM * NCOMB];

static __device__ int g_cnt_i[RREL * NI];
static __device__ int g_cnt_u[RREL * NU];
static __device__ int g_bkt_i[(size_t)RREL * NI * CAP_I];
static __device__ int g_bkt_u[(size_t)RREL * NU * CAP_U];
static __device__ int g_ovf_i[MAXOVF];
static __device__ int g_ovf_u[MAXOVF];
static __device__ int g_ovfcnt[2];

// ---------------------------------------------------------------------------
// Kernel 1: combine weights  Wc[k][r*128+o] = sum_m W[r,k,m] * Wfc[r*128+m, o]
// ---------------------------------------------------------------------------
__global__ void combine_w_kernel(const float* __restrict__ W,
                                 const float* __restrict__ Wfc,
                                 float* __restrict__ Wc)
{
    int idx = blockIdx.x * blockDim.x + threadIdx.x;
    if (idx >= KDIM * NCOMB) return;
    int k = idx / NCOMB;
    int c = idx - k * NCOMB;
    int r = c / OUTD;
    int o = c - r * OUTD;
    const float* wrow = W + ((size_t)r * KDIM + k) * MSGD;
    const float* fc   = Wfc + ((size_t)r * MSGD) * OUTD + o;
    float s = 0.f;
#pragma unroll 8
    for (int m = 0; m < MSGD; ++m)
        s += wrow[m] * fc[(size_t)m * OUTD];
    Wc[idx] = s;
}

// ---------------------------------------------------------------------------
// Zero helpers
// ---------------------------------------------------------------------------
__global__ void zero_int_kernel(int4* __restrict__ p, int n4)
{
    int i = blockIdx.x * blockDim.x + threadIdx.x;
    if (i < n4) p[i] = make_int4(0, 0, 0, 0);
}

__global__ void zero_ovf_kernel(int* p)
{
    if (threadIdx.x < 2) p[threadIdx.x] = 0;
}

// ---------------------------------------------------------------------------
// fp16 helpers
// ---------------------------------------------------------------------------
__device__ __forceinline__ uint2 f4_to_h4(float4 v)
{
    __half2 lo = __float22half2_rn(make_float2(v.x, v.y));
    __half2 hi = __float22half2_rn(make_float2(v.z, v.w));
    uint2 r;
    r.x = *(uint32_t*)&lo;
    r.y = *(uint32_t*)&hi;
    return r;
}

// ---------------------------------------------------------------------------
// Kernel 3: FP16 tensor-core GEMM (fp32 accumulate), fp16 output.
// X layout: [R][M][128] half; block column index == relation.
// Epilogue stages the 128x128 half tile through smem (aliasing the pipeline
// buffers after the mainloop) for fully coalesced 16B global stores.
// ---------------------------------------------------------------------------
__global__ __launch_bounds__(256, 2) void gemm_f16_kernel(
    const float* __restrict__ A,    // [M, 256] fp32
    const float* __restrict__ Bw,   // [256, 640] fp32
    const float* __restrict__ cj,   // [M]
    __half* __restrict__ X,         // [R][M][128] fp16
    int M)
{
    constexpr int LDA = 24;    // halfs per A row (16 + 8 pad)
    constexpr int LDB = 136;   // halfs per B row (128 + 8 pad)
    constexpr int LDT = 136;   // halfs per epilogue tile row
    // union: pipeline (As 6144 + Bs 4352 halfs = 20992B) vs out tile (17408 halfs = 34816B)
    __shared__ __align__(16) __half smem_u[128 * LDT];

    __half* AsBase = smem_u;                       // 2 x 128 x LDA
    __half* BsBase = smem_u + 2 * 128 * LDA;       // 2 x 16 x LDB

    const int t    = threadIdx.x;
    const int lane = t & 31;
    const int warp = t >> 5;
    const int wm   = (warp >> 2) * 64;     // 0 or 64
    const int wn   = (warp & 3) * 32;      // 0,32,64,96
    const int rowBase = blockIdx.y * 128;

    const int aRow = t >> 2;               // 0..63 (plus +64)
    const int aCol = (t & 3) << 2;         // k offset 0,4,8,12
    const int bRow = t >> 5;               // 0..7 (plus +8)
    const int bCol = (t & 31) << 2;        // n offset 0..124

    const bool v0 = (rowBase + aRow)      < M;
    const bool v1 = (rowBase + aRow + 64) < M;
    const float* Aptr0 = A + (size_t)(rowBase + aRow) * KDIM + aCol;
    const float* Aptr1 = Aptr0 + (size_t)64 * KDIM;
    const float* Bptr0 = Bw + (size_t)bRow * NCOMB + blockIdx.x * 128 + bCol;
    const float* Bptr1 = Bptr0 + (size_t)8 * NCOMB;

    const float4 f4z = make_float4(0.f, 0.f, 0.f, 0.f);

    float acc[4][4][4];
#pragma unroll
    for (int mt = 0; mt < 4; ++mt)
#pragma unroll
        for (int nt = 0; nt < 4; ++nt)
#pragma unroll
            for (int c = 0; c < 4; ++c) acc[mt][nt][c] = 0.f;

    const int aLdRow = wm + (lane & 15);
    const int aLdK   = ((lane >> 4) & 1) * 8;
    const int bLdK = lane & 15;
    const int bLdN = ((lane >> 4) & 1) * 8;

    float4 pa0, pa1, pb0, pb1;

    pa0 = v0 ? *(const float4*)(Aptr0) : f4z;
    pa1 = v1 ? *(const float4*)(Aptr1) : f4z;
    pb0 = *(const float4*)(Bptr0);
    pb1 = *(const float4*)(Bptr1);
    {
        __half* as = AsBase; __half* bs = BsBase;
        *(uint2*)&as[aRow * LDA + aCol]        = f4_to_h4(pa0);
        *(uint2*)&as[(aRow + 64) * LDA + aCol] = f4_to_h4(pa1);
        *(uint2*)&bs[bRow * LDB + bCol]        = f4_to_h4(pb0);
        *(uint2*)&bs[(bRow + 8) * LDB + bCol]  = f4_to_h4(pb1);
    }
    __syncthreads();

    for (int s = 0; s < 16; ++s) {
        const int nxt = s + 1;
        if (nxt < 16) {
            const int k0 = nxt * 16;
            pa0 = v0 ? *(const float4*)(Aptr0 + k0) : f4z;
            pa1 = v1 ? *(const float4*)(Aptr1 + k0) : f4z;
            pb0 = *(const float4*)(Bptr0 + (size_t)k0 * NCOMB);
            pb1 = *(const float4*)(Bptr1 + (size_t)k0 * NCOMB);
        }

        const int buf = s & 1;
        const uint32_t asb = (uint32_t)__cvta_generic_to_shared(AsBase + buf * 128 * LDA);
        const uint32_t bsb = (uint32_t)__cvta_generic_to_shared(BsBase + buf * 16 * LDB);

        uint32_t af[4][4];
#pragma unroll
        for (int mt = 0; mt < 4; ++mt) {
            uint32_t addr = asb +
                (uint32_t)(((aLdRow + mt * 16) * LDA + aLdK) * 2);
            asm volatile(
                "ldmatrix.sync.aligned.m8n8.x4.shared.b16 {%0,%1,%2,%3}, [%4];"
                : "=r"(af[mt][0]), "=r"(af[mt][1]),
                  "=r"(af[mt][2]), "=r"(af[mt][3])
                : "r"(addr));
        }
        uint32_t bf[4][2];
#pragma unroll
        for (int np = 0; np < 2; ++np) {
            uint32_t addr = bsb +
                (uint32_t)((bLdK * LDB + wn + np * 16 + bLdN) * 2);
            uint32_t r0, r1, r2, r3;
            asm volatile(
                "ldmatrix.sync.aligned.m8n8.x4.trans.shared.b16 {%0,%1,%2,%3}, [%4];"
                : "=r"(r0), "=r"(r1), "=r"(r2), "=r"(r3)
                : "r"(addr));
            bf[np * 2 + 0][0] = r0; bf[np * 2 + 0][1] = r1;
            bf[np * 2 + 1][0] = r2; bf[np * 2 + 1][1] = r3;
        }

#pragma unroll
        for (int mt = 0; mt < 4; ++mt)
#pragma unroll
            for (int nt = 0; nt < 4; ++nt) {
                asm volatile(
                    "mma.sync.aligned.m16n8k16.row.col.f32.f16.f16.f32 "
                    "{%0,%1,%2,%3}, {%4,%5,%6,%7}, {%8,%9}, {%0,%1,%2,%3};"
                    : "+f"(acc[mt][nt][0]), "+f"(acc[mt][nt][1]),
                      "+f"(acc[mt][nt][2]), "+f"(acc[mt][nt][3])
                    : "r"(af[mt][0]), "r"(af[mt][1]),
                      "r"(af[mt][2]), "r"(af[mt][3]),
                      "r"(bf[nt][0]), "r"(bf[nt][1]));
            }

        if (nxt < 16) {
            __half* asn = AsBase + (nxt & 1) * 128 * LDA;
            __half* bsn = BsBase + (nxt & 1) * 16 * LDB;
            *(uint2*)&asn[aRow * LDA + aCol]        = f4_to_h4(pa0);
            *(uint2*)&asn[(aRow + 64) * LDA + aCol] = f4_to_h4(pa1);
            *(uint2*)&bsn[bRow * LDB + bCol]        = f4_to_h4(pb0);
            *(uint2*)&bsn[(bRow + 8) * LDB + bCol]  = f4_to_h4(pb1);
        }
        __syncthreads();
    }

    // ---- epilogue: scale by cj, stage fp16 tile in smem, coalesced store ----
    __half* tile = smem_u;   // aliases pipeline buffers (all reads done)
#pragma unroll
    for (int mt = 0; mt < 4; ++mt) {
        const int lr0 = wm + mt * 16 + (lane >> 2);
        const int lr1 = lr0 + 8;
        const int r0 = rowBase + lr0;
        const int r1 = rowBase + lr1;
        const float c0s = (r0 < M) ? __ldg(cj + r0) : 0.f;
        const float c1s = (r1 < M) ? __ldg(cj + r1) : 0.f;
#pragma unroll
        for (int nt = 0; nt < 4; ++nt) {
            const int col = wn + nt * 8 + (lane & 3) * 2;
            *(half2*)&tile[lr0 * LDT + col] =
                __floats2half2_rn(acc[mt][nt][0] * c0s, acc[mt][nt][1] * c0s);
            *(half2*)&tile[lr1 * LDT + col] =
                __floats2half2_rn(acc[mt][nt][2] * c1s, acc[mt][nt][3] * c1s);
        }
    }
    __syncthreads();

    __half* Xr = X + (size_t)blockIdx.x * M * OUTD;
#pragma unroll
    for (int idx = t; idx < 128 * 16; idx += 256) {
        int row = idx >> 4;
        int seg = idx & 15;
        int gr = rowBase + row;
        if (gr < M)
            *(uint4*)(Xr + (size_t)gr * OUTD + seg * 8) =
                *(const uint4*)&tile[row * LDT + seg * 8];
    }
}

// ---------------------------------------------------------------------------
// Kernel 4a: bin edges by (relation, dst) into fixed-capacity buckets.
// ---------------------------------------------------------------------------
template <int N, int CAP>
__global__ __launch_bounds__(256) void bin_kernel(
    const int* __restrict__ dstArr,   // [R*E]
    const int* __restrict__ srcArr,   // [R*E]
    int* __restrict__ cnt,            // [R*N]
    int* __restrict__ bkt,            // [R*N*CAP]
    int* __restrict__ ovf,
    int* __restrict__ ovfcnt)
{
    int w = blockIdx.x * 256 + threadIdx.x;
    if (w >= RREL * NE) return;
    int r = w / NE;
    int key = r * N + dstArr[w];
    int pos = atomicAdd(&cnt[key], 1);
    if (pos < CAP) {
        bkt[(size_t)key * CAP + pos] = srcArr[w];
    } else {
        int o = atomicAdd(ovfcnt, 1);
        if (o < MAXOVF) ovf[o] = w;
    }
}

// ---------------------------------------------------------------------------
// Kernel 4b: fused gather + finalize. One warp per destination node:
// accumulate all 5 relation buckets in registers, then ONE plain float4
// store of ci*s + bias directly into the output (no acc buffer, no atomics).
// ---------------------------------------------------------------------------
template <int N, int CAP, int MSRC>
__global__ __launch_bounds__(256) void gather_out_kernel(
    const __half* __restrict__ X,     // [R][MSRC][128] fp16
    const int* __restrict__ cnt,      // [R*N]
    const int* __restrict__ bkt,      // [R*N*CAP]
    const float* __restrict__ ci,     // [N]
    const float* __restrict__ bias,   // [128]
    float* __restrict__ out)          // [N, 128]
{
    int dst = blockIdx.x * 8 + (threadIdx.x >> 5);
    if (dst >= N) return;
    int lane = threadIdx.x & 31;
    const __half* Xl = X + (size_t)lane * 4;

    float4 s = make_float4(0.f, 0.f, 0.f, 0.f);
#pragma unroll
    for (int r = 0; r < RREL; ++r) {
        int key = r * N + dst;
        int n = cnt[key];
        int m = n < CAP ? n : CAP;
        const int* b = bkt + (size_t)key * CAP;
        const __half* Xr = Xl + (size_t)r * MSRC * OUTD;
#pragma unroll 8
        for (int i = 0; i < m; ++i) {
            int src = b[i];
            uint2 raw = *(const uint2*)(Xr + (size_t)src * OUTD);
            float2 f0 = __half22float2(*(const __half2*)&raw.x);
            float2 f1 = __half22float2(*(const __half2*)&raw.y);
            s.x += f0.x; s.y += f0.y; s.z += f1.x; s.w += f1.y;
        }
    }

    float c = ci[dst];
    float4 bb = *(const float4*)(bias + lane * 4);
    float4 o;
    o.x = s.x * c + bb.x; o.y = s.y * c + bb.y;
    o.z = s.z * c + bb.z; o.w = s.w * c + bb.w;
    *(float4*)(out + (size_t)dst * OUTD + lane * 4) = o;
}

// ---------------------------------------------------------------------------
// Kernel 4c: overflow fallback (expected empty): red.add ci*msg into out.
// ---------------------------------------------------------------------------
template <int MSRC>
__global__ __launch_bounds__(256) void ovf_kernel(
    const __half* __restrict__ X,
    const int* __restrict__ srcArr,
    const int* __restrict__ dstArr,
    const int* __restrict__ ovf,
    const int* __restrict__ ovfcnt,
    const float* __restrict__ ci,
    float* __restrict__ out)
{
    int nov = *ovfcnt;
    if (nov > MAXOVF) nov = MAXOVF;
    int lane = threadIdx.x & 31;
    for (int idx = blockIdx.x * 8 + (threadIdx.x >> 5); idx < nov;
         idx += gridDim.x * 8) {
        int w = ovf[idx];
        int r = w / NE;
        int src = srcArr[w];
        int dst = dstArr[w];
        float c = ci[dst];
        uint2 raw = *(const uint2*)(X + ((size_t)r * MSRC + src) * OUTD + lane * 4);
        float2 f0 = __half22float2(*(const __half2*)&raw.x);
        float2 f1 = __half22float2(*(const __half2*)&raw.y);
        float* ap = out + (size_t)dst * OUTD + lane * 4;
        asm volatile("red.global.add.v4.f32 [%0], {%1, %2, %3, %4};"
                     :: "l"(ap), "f"(f0.x * c), "f"(f0.y * c),
                        "f"(f1.x * c), "f"(f1.y * c)
                     : "memory");
    }
}

// ---------------------------------------------------------------------------
// Host launcher
// ---------------------------------------------------------------------------
extern "C" void kernel_launch(void* const* d_in, const int* in_sizes, int n_in,
                              void* d_out, int out_size)
{
    const float* ufeat   = (const float*)d_in[0];
    const float* ifeat   = (const float*)d_in[1];
    const float* cj_user = (const float*)d_in[2];
    const float* ci_user = (const float*)d_in[3];
    const float* cj_item = (const float*)d_in[4];
    const float* ci_item = (const float*)d_in[5];
    const float* W_u     = (const float*)d_in[6];
    const float* W_i     = (const float*)d_in[7];
    const float* Wu_fc   = (const float*)d_in[8];
    const float* bu      = (const float*)d_in[9];
    const float* Wi_fc   = (const float*)d_in[10];
    const float* bi      = (const float*)d_in[11];
    const int*   edge_u  = (const int*)d_in[12];
    const int*   edge_i  = (const int*)d_in[13];
    float* out = (float*)d_out;
    float* out_u = out;
    float* out_i = out + (size_t)NU * OUTD;

    __half *xu, *xi;
    float *wcu, *wci;
    int *cnt_i, *cnt_u, *bkt_i, *bkt_u, *ovf_i, *ovf_u, *ovfc;
    cudaGetSymbolAddress((void**)&xu,    g_xu);
    cudaGetSymbolAddress((void**)&xi,    g_xi);
    cudaGetSymbolAddress((void**)&wcu,   g_wcu);
    cudaGetSymbolAddress((void**)&wci,   g_wci);
    cudaGetSymbolAddress((void**)&cnt_i, g_cnt_i);
    cudaGetSymbolAddress((void**)&cnt_u, g_cnt_u);
    cudaGetSymbolAddress((void**)&bkt_i, g_bkt_i);
    cudaGetSymbolAddress((void**)&bkt_u, g_bkt_u);
    cudaGetSymbolAddress((void**)&ovf_i, g_ovf_i);
    cudaGetSymbolAddress((void**)&ovf_u, g_ovf_u);
    cudaGetSymbolAddress((void**)&ovfc,  g_ovfcnt);

    // 1) Fold per-relation projection into FC slice.
    int ctotal = KDIM * NCOMB;
    combine_w_kernel<<<(ctotal + 255) / 256, 256>>>(W_u, Wi_fc, wcu);
    combine_w_kernel<<<(ctotal + 255) / 256, 256>>>(W_i, Wu_fc, wci);

    // 2) Zero degree counters + overflow counters.
    zero_int_kernel<<<((RREL * NI / 4) + 255) / 256, 256>>>((int4*)cnt_i, RREL * NI / 4);
    zero_int_kernel<<<((RREL * NU / 4) + 255) / 256, 256>>>((int4*)cnt_u, RREL * NU / 4);
    zero_ovf_kernel<<<1, 32>>>(ovfc);

    // 3) Bin edges by (relation, dst).
    int bblocks = (RREL * NE + 255) / 256;
    bin_kernel<NI, CAP_I><<<bblocks, 256>>>(edge_i, edge_u, cnt_i, bkt_i, ovf_i, ovfc + 0);
    bin_kernel<NU, CAP_U><<<bblocks, 256>>>(edge_u, edge_i, cnt_u, bkt_u, ovf_u, ovfc + 1);

    // 4) Fused message GEMMs on FP16 tensor cores, fp16 message output.
    dim3 gu(NCOMB / 128, (NU + 127) / 128);
    gemm_f16_kernel<<<gu, 256>>>(ufeat, wcu, cj_user, xu, NU);
    dim3 gi(NCOMB / 128, (NI + 127) / 128);
    gemm_f16_kernel<<<gi, 256>>>(ifeat, wci, cj_item, xi, NI);

    // 5) Fused gather + finalize, straight into d_out (one warp per dst node).
    gather_out_kernel<NI, CAP_I, NU><<<(NI + 7) / 8, 256>>>(
        xu, cnt_i, bkt_i, ci_item, bi, out_i);
    gather_out_kernel<NU, CAP_U, NI><<<(NU + 7) / 8, 256>>>(
        xi, cnt_u, bkt_u, ci_user, bu, out_u);

    // 6) Overflow fallback (normally zero work).
    ovf_kernel<NU><<<256, 256>>>(xu, edge_u, edge_i, ovf_i, ovfc + 0, ci_item, out_i);
    ovf_kernel<NI><<<256, 256>>>(xi, edge_i, edge_u, ovf_u, ovfc + 1, ci_user, out_u);
}

// round 16
// speedup vs baseline: 3.4067x; 1.0369x over previous
#include <cuda_runtime.h>
#include <cuda_fp16.h>
#include <cstdint>
#include <cstddef>

// ---------------------------------------------------------------------------
// Problem constants (fixed shapes per reference)
// ---------------------------------------------------------------------------
#define NU    100000
#define NI    50000
#define KDIM  256
#define MSGD  128
#define OUTD  128
#define RREL  5
#define NE    1000000
#define NCOMB (RREL * OUTD)   // 640

#define CAP_I 64              // bucket capacity per (r, item) — mean deg 20
#define CAP_U 40              // bucket capacity per (r, user) — mean deg 10
#define MAXOVF (1 << 20)

// ---------------------------------------------------------------------------
// Static device scratch (no runtime allocation allowed)
// ---------------------------------------------------------------------------
static __device__ __half g_xu[(size_t)RREL * NU * OUTD];  // messages fp16, [R][NU][128]
static __device__ __half g_xi[(size_t)RREL * NI * OUTD];  // messages fp16, [R][NI][128]
static __device__ float g_wcu[KDIM * NCOMB];
static __device__ float g_wci[KDIM * NCOMB];

static __device__ int g_cnt_i[RREL * NI];
static __device__ int g_cnt_u[RREL * NU];
static __device__ int g_bkt_i[(size_t)RREL * NI * CAP_I];
static __device__ int g_bkt_u[(size_t)RREL * NU * CAP_U];
static __device__ int g_ovf_i[MAXOVF];
static __device__ int g_ovf_u[MAXOVF];
static __device__ int g_ovfcnt[2];

// ---------------------------------------------------------------------------
// Kernel 1: combine weights  Wc[k][r*128+o] = sum_m W[r,k,m] * Wfc[r*128+m, o]
// ---------------------------------------------------------------------------
__global__ void combine_w_kernel(const float* __restrict__ W,
                                 const float* __restrict__ Wfc,
                                 float* __restrict__ Wc)
{
    int idx = blockIdx.x * blockDim.x + threadIdx.x;
    if (idx >= KDIM * NCOMB) return;
    int k = idx / NCOMB;
    int c = idx - k * NCOMB;
    int r = c / OUTD;
    int o = c - r * OUTD;
    const float* wrow = W + ((size_t)r * KDIM + k) * MSGD;
    const float* fc   = Wfc + ((size_t)r * MSGD) * OUTD + o;
    float s = 0.f;
#pragma unroll 8
    for (int m = 0; m < MSGD; ++m)
        s += wrow[m] * fc[(size_t)m * OUTD];
    Wc[idx] = s;
}

// ---------------------------------------------------------------------------
// Zero helpers
// ---------------------------------------------------------------------------
__global__ void zero_int_kernel(int4* __restrict__ p, int n4)
{
    int i = blockIdx.x * blockDim.x + threadIdx.x;
    if (i < n4) p[i] = make_int4(0, 0, 0, 0);
}

__global__ void zero_ovf_kernel(int* p)
{
    if (threadIdx.x < 2) p[threadIdx.x] = 0;
}

// ---------------------------------------------------------------------------
// fp16 helpers
// ---------------------------------------------------------------------------
__device__ __forceinline__ uint2 f4_to_h4(float4 v)
{
    __half2 lo = __float22half2_rn(make_float2(v.x, v.y));
    __half2 hi = __float22half2_rn(make_float2(v.z, v.w));
    uint2 r;
    r.x = *(uint32_t*)&lo;
    r.y = *(uint32_t*)&hi;
    return r;
}

// ---------------------------------------------------------------------------
// Kernel 3: FP16 tensor-core GEMM (fp32 accumulate), fp16 output.
// X layout: [R][M][128] half; block column index == relation.
// ---------------------------------------------------------------------------
__global__ __launch_bounds__(256, 2) void gemm_f16_kernel(
    const float* __restrict__ A,    // [M, 256] fp32
    const float* __restrict__ Bw,   // [256, 640] fp32
    const float* __restrict__ cj,   // [M]
    __half* __restrict__ X,         // [R][M][128] fp16
    int M)
{
    constexpr int LDA = 24;    // halfs per A row (16 + 8 pad)
    constexpr int LDB = 136;   // halfs per B row (128 + 8 pad)
    constexpr int LDT = 136;   // halfs per epilogue tile row
    __shared__ __align__(16) __half smem_u[128 * LDT];

    __half* AsBase = smem_u;                       // 2 x 128 x LDA
    __half* BsBase = smem_u + 2 * 128 * LDA;       // 2 x 16 x LDB

    const int t    = threadIdx.x;
    const int lane = t & 31;
    const int warp = t >> 5;
    const int wm   = (warp >> 2) * 64;
    const int wn   = (warp & 3) * 32;
    const int rowBase = blockIdx.y * 128;

    const int aRow = t >> 2;
    const int aCol = (t & 3) << 2;
    const int bRow = t >> 5;
    const int bCol = (t & 31) << 2;

    const bool v0 = (rowBase + aRow)      < M;
    const bool v1 = (rowBase + aRow + 64) < M;
    const float* Aptr0 = A + (size_t)(rowBase + aRow) * KDIM + aCol;
    const float* Aptr1 = Aptr0 + (size_t)64 * KDIM;
    const float* Bptr0 = Bw + (size_t)bRow * NCOMB + blockIdx.x * 128 + bCol;
    const float* Bptr1 = Bptr0 + (size_t)8 * NCOMB;

    const float4 f4z = make_float4(0.f, 0.f, 0.f, 0.f);

    float acc[4][4][4];
#pragma unroll
    for (int mt = 0; mt < 4; ++mt)
#pragma unroll
        for (int nt = 0; nt < 4; ++nt)
#pragma unroll
            for (int c = 0; c < 4; ++c) acc[mt][nt][c] = 0.f;

    const int aLdRow = wm + (lane & 15);
    const int aLdK   = ((lane >> 4) & 1) * 8;
    const int bLdK = lane & 15;
    const int bLdN = ((lane >> 4) & 1) * 8;

    float4 pa0, pa1, pb0, pb1;

    pa0 = v0 ? *(const float4*)(Aptr0) : f4z;
    pa1 = v1 ? *(const float4*)(Aptr1) : f4z;
    pb0 = *(const float4*)(Bptr0);
    pb1 = *(const float4*)(Bptr1);
    {
        __half* as = AsBase; __half* bs = BsBase;
        *(uint2*)&as[aRow * LDA + aCol]        = f4_to_h4(pa0);
        *(uint2*)&as[(aRow + 64) * LDA + aCol] = f4_to_h4(pa1);
        *(uint2*)&bs[bRow * LDB + bCol]        = f4_to_h4(pb0);
        *(uint2*)&bs[(bRow + 8) * LDB + bCol]  = f4_to_h4(pb1);
    }
    __syncthreads();

    for (int s = 0; s < 16; ++s) {
        const int nxt = s + 1;
        if (nxt < 16) {
            const int k0 = nxt * 16;
            pa0 = v0 ? *(const float4*)(Aptr0 + k0) : f4z;
            pa1 = v1 ? *(const float4*)(Aptr1 + k0) : f4z;
            pb0 = *(const float4*)(Bptr0 + (size_t)k0 * NCOMB);
            pb1 = *(const float4*)(Bptr1 + (size_t)k0 * NCOMB);
        }

        const int buf = s & 1;
        const uint32_t asb = (uint32_t)__cvta_generic_to_shared(AsBase + buf * 128 * LDA);
        const uint32_t bsb = (uint32_t)__cvta_generic_to_shared(BsBase + buf * 16 * LDB);

        uint32_t af[4][4];
#pragma unroll
        for (int mt = 0; mt < 4; ++mt) {
            uint32_t addr = asb +
                (uint32_t)(((aLdRow + mt * 16) * LDA + aLdK) * 2);
            asm volatile(
                "ldmatrix.sync.aligned.m8n8.x4.shared.b16 {%0,%1,%2,%3}, [%4];"
                : "=r"(af[mt][0]), "=r"(af[mt][1]),
                  "=r"(af[mt][2]), "=r"(af[mt][3])
                : "r"(addr));
        }
        uint32_t bf[4][2];
#pragma unroll
        for (int np = 0; np < 2; ++np) {
            uint32_t addr = bsb +
                (uint32_t)((bLdK * LDB + wn + np * 16 + bLdN) * 2);
            uint32_t r0, r1, r2, r3;
            asm volatile(
                "ldmatrix.sync.aligned.m8n8.x4.trans.shared.b16 {%0,%1,%2,%3}, [%4];"
                : "=r"(r0), "=r"(r1), "=r"(r2), "=r"(r3)
                : "r"(addr));
            bf[np * 2 + 0][0] = r0; bf[np * 2 + 0][1] = r1;
            bf[np * 2 + 1][0] = r2; bf[np * 2 + 1][1] = r3;
        }

#pragma unroll
        for (int mt = 0; mt < 4; ++mt)
#pragma unroll
            for (int nt = 0; nt < 4; ++nt) {
                asm volatile(
                    "mma.sync.aligned.m16n8k16.row.col.f32.f16.f16.f32 "
                    "{%0,%1,%2,%3}, {%4,%5,%6,%7}, {%8,%9}, {%0,%1,%2,%3};"
                    : "+f"(acc[mt][nt][0]), "+f"(acc[mt][nt][1]),
                      "+f"(acc[mt][nt][2]), "+f"(acc[mt][nt][3])
                    : "r"(af[mt][0]), "r"(af[mt][1]),
                      "r"(af[mt][2]), "r"(af[mt][3]),
                      "r"(bf[nt][0]), "r"(bf[nt][1]));
            }

        if (nxt < 16) {
            __half* asn = AsBase + (nxt & 1) * 128 * LDA;
            __half* bsn = BsBase + (nxt & 1) * 16 * LDB;
            *(uint2*)&asn[aRow * LDA + aCol]        = f4_to_h4(pa0);
            *(uint2*)&asn[(aRow + 64) * LDA + aCol] = f4_to_h4(pa1);
            *(uint2*)&bsn[bRow * LDB + bCol]        = f4_to_h4(pb0);
            *(uint2*)&bsn[(bRow + 8) * LDB + bCol]  = f4_to_h4(pb1);
        }
        __syncthreads();
    }

    // ---- epilogue: scale by cj, stage fp16 tile in smem, coalesced store ----
    __half* tile = smem_u;
#pragma unroll
    for (int mt = 0; mt < 4; ++mt) {
        const int lr0 = wm + mt * 16 + (lane >> 2);
        const int lr1 = lr0 + 8;
        const int r0 = rowBase + lr0;
        const int r1 = rowBase + lr1;
        const float c0s = (r0 < M) ? __ldg(cj + r0) : 0.f;
        const float c1s = (r1 < M) ? __ldg(cj + r1) : 0.f;
#pragma unroll
        for (int nt = 0; nt < 4; ++nt) {
            const int col = wn + nt * 8 + (lane & 3) * 2;
            *(half2*)&tile[lr0 * LDT + col] =
                __floats2half2_rn(acc[mt][nt][0] * c0s, acc[mt][nt][1] * c0s);
            *(half2*)&tile[lr1 * LDT + col] =
                __floats2half2_rn(acc[mt][nt][2] * c1s, acc[mt][nt][3] * c1s);
        }
    }
    __syncthreads();

    __half* Xr = X + (size_t)blockIdx.x * M * OUTD;
#pragma unroll
    for (int idx = t; idx < 128 * 16; idx += 256) {
        int row = idx >> 4;
        int seg = idx & 15;
        int gr = rowBase + row;
        if (gr < M)
            *(uint4*)(Xr + (size_t)gr * OUTD + seg * 8) =
                *(const uint4*)&tile[row * LDT + seg * 8];
    }
}

// ---------------------------------------------------------------------------
// Kernel 4a: bin edges by (relation, dst) into fixed-capacity buckets.
// ---------------------------------------------------------------------------
template <int N, int CAP>
__global__ __launch_bounds__(256) void bin_kernel(
    const int* __restrict__ dstArr,   // [R*E]
    const int* __restrict__ srcArr,   // [R*E]
    int* __restrict__ cnt,            // [R*N]
    int* __restrict__ bkt,            // [R*N*CAP]
    int* __restrict__ ovf,
    int* __restrict__ ovfcnt)
{
    int w = blockIdx.x * 256 + threadIdx.x;
    if (w >= RREL * NE) return;
    int r = w / NE;
    int key = r * N + dstArr[w];
    int pos = atomicAdd(&cnt[key], 1);
    if (pos < CAP) {
        bkt[(size_t)key * CAP + pos] = srcArr[w];
    } else {
        int o = atomicAdd(ovfcnt, 1);
        if (o < MAXOVF) ovf[o] = w;
    }
}

// ---------------------------------------------------------------------------
// Kernel 4b: fused gather + finalize. One warp per destination node.
// ---------------------------------------------------------------------------
template <int N, int CAP, int MSRC>
__global__ __launch_bounds__(256) void gather_out_kernel(
    const __half* __restrict__ X,     // [R][MSRC][128] fp16
    const int* __restrict__ cnt,      // [R*N]
    const int* __restrict__ bkt,      // [R*N*CAP]
    const float* __restrict__ ci,     // [N]
    const float* __restrict__ bias,   // [128]
    float* __restrict__ out)          // [N, 128]
{
    int dst = blockIdx.x * 8 + (threadIdx.x >> 5);
    if (dst >= N) return;
    int lane = threadIdx.x & 31;
    const __half* Xl = X + (size_t)lane * 4;

    float4 s = make_float4(0.f, 0.f, 0.f, 0.f);
#pragma unroll
    for (int r = 0; r < RREL; ++r) {
        int key = r * N + dst;
        int n = cnt[key];
        int m = n < CAP ? n : CAP;
        const int* b = bkt + (size_t)key * CAP;
        const __half* Xr = Xl + (size_t)r * MSRC * OUTD;
#pragma unroll 8
        for (int i = 0; i < m; ++i) {
            int src = b[i];
            uint2 raw = *(const uint2*)(Xr + (size_t)src * OUTD);
            float2 f0 = __half22float2(*(const __half2*)&raw.x);
            float2 f1 = __half22float2(*(const __half2*)&raw.y);
            s.x += f0.x; s.y += f0.y; s.z += f1.x; s.w += f1.y;
        }
    }

    float c = ci[dst];
    float4 bb = *(const float4*)(bias + lane * 4);
    float4 o;
    o.x = s.x * c + bb.x; o.y = s.y * c + bb.y;
    o.z = s.z * c + bb.z; o.w = s.w * c + bb.w;
    *(float4*)(out + (size_t)dst * OUTD + lane * 4) = o;
}

// ---------------------------------------------------------------------------
// Kernel 4c: overflow fallback (expected empty): red.add ci*msg into out.
// ---------------------------------------------------------------------------
template <int MSRC>
__global__ __launch_bounds__(256) void ovf_kernel(
    const __half* __restrict__ X,
    const int* __restrict__ srcArr,
    const int* __restrict__ dstArr,
    const int* __restrict__ ovf,
    const int* __restrict__ ovfcnt,
    const float* __restrict__ ci,
    float* __restrict__ out)
{
    int nov = *ovfcnt;
    if (nov > MAXOVF) nov = MAXOVF;
    int lane = threadIdx.x & 31;
    for (int idx = blockIdx.x * 8 + (threadIdx.x >> 5); idx < nov;
         idx += gridDim.x * 8) {
        int w = ovf[idx];
        int r = w / NE;
        int src = srcArr[w];
        int dst = dstArr[w];
        float c = ci[dst];
        uint2 raw = *(const uint2*)(X + ((size_t)r * MSRC + src) * OUTD + lane * 4);
        float2 f0 = __half22float2(*(const __half2*)&raw.x);
        float2 f1 = __half22float2(*(const __half2*)&raw.y);
        float* ap = out + (size_t)dst * OUTD + lane * 4;
        asm volatile("red.global.add.v4.f32 [%0], {%1, %2, %3, %4};"
                     :: "l"(ap), "f"(f0.x * c), "f"(f0.y * c),
                        "f"(f1.x * c), "f"(f1.y * c)
                     : "memory");
    }
}

// ---------------------------------------------------------------------------
// Host launcher — fork/join concurrency: bin pipeline runs on an aux stream
// concurrently with the GEMM pipeline; both join before the gathers.
// Stream/event objects are created once on the first (uncaptured) call.
// ---------------------------------------------------------------------------
extern "C" void kernel_launch(void* const* d_in, const int* in_sizes, int n_in,
                              void* d_out, int out_size)
{
    const float* ufeat   = (const float*)d_in[0];
    const float* ifeat   = (const float*)d_in[1];
    const float* cj_user = (const float*)d_in[2];
    const float* ci_user = (const float*)d_in[3];
    const float* cj_item = (const float*)d_in[4];
    const float* ci_item = (const float*)d_in[5];
    const float* W_u     = (const float*)d_in[6];
    const float* W_i     = (const float*)d_in[7];
    const float* Wu_fc   = (const float*)d_in[8];
    const float* bu      = (const float*)d_in[9];
    const float* Wi_fc   = (const float*)d_in[10];
    const float* bi      = (const float*)d_in[11];
    const int*   edge_u  = (const int*)d_in[12];
    const int*   edge_i  = (const int*)d_in[13];
    float* out = (float*)d_out;
    float* out_u = out;
    float* out_i = out + (size_t)NU * OUTD;

    __half *xu, *xi;
    float *wcu, *wci;
    int *cnt_i, *cnt_u, *bkt_i, *bkt_u, *ovf_i, *ovf_u, *ovfc;
    cudaGetSymbolAddress((void**)&xu,    g_xu);
    cudaGetSymbolAddress((void**)&xi,    g_xi);
    cudaGetSymbolAddress((void**)&wcu,   g_wcu);
    cudaGetSymbolAddress((void**)&wci,   g_wci);
    cudaGetSymbolAddress((void**)&cnt_i, g_cnt_i);
    cudaGetSymbolAddress((void**)&cnt_u, g_cnt_u);
    cudaGetSymbolAddress((void**)&bkt_i, g_bkt_i);
    cudaGetSymbolAddress((void**)&bkt_u, g_bkt_u);
    cudaGetSymbolAddress((void**)&ovf_i, g_ovf_i);
    cudaGetSymbolAddress((void**)&ovf_u, g_ovf_u);
    cudaGetSymbolAddress((void**)&ovfc,  g_ovfcnt);

    // One-time infra (created on the uncaptured correctness call; reused in
    // capture). Objects only — the enqueued work DAG is identical every call.
    static cudaStream_t s_aux = nullptr;
    static cudaEvent_t ev_fork = nullptr, ev_join = nullptr;
    if (s_aux == nullptr) {
        cudaStreamCreateWithFlags(&s_aux, cudaStreamNonBlocking);
        cudaEventCreateWithFlags(&ev_fork, cudaEventDisableTiming);
        cudaEventCreateWithFlags(&ev_join, cudaEventDisableTiming);
    }

    // ---- fork: aux stream joins the capture DAG ----
    cudaEventRecord(ev_fork, 0);
    cudaStreamWaitEvent(s_aux, ev_fork, 0);

    // ---- aux stream: zero counters, then bin edges (atomic/scatter-bound) ----
    zero_int_kernel<<<((RREL * NI / 4) + 255) / 256, 256, 0, s_aux>>>(
        (int4*)cnt_i, RREL * NI / 4);
    zero_int_kernel<<<((RREL * NU / 4) + 255) / 256, 256, 0, s_aux>>>(
        (int4*)cnt_u, RREL * NU / 4);
    zero_ovf_kernel<<<1, 32, 0, s_aux>>>(ovfc);
    int bblocks = (RREL * NE + 255) / 256;
    bin_kernel<NI, CAP_I><<<bblocks, 256, 0, s_aux>>>(
        edge_i, edge_u, cnt_i, bkt_i, ovf_i, ovfc + 0);
    bin_kernel<NU, CAP_U><<<bblocks, 256, 0, s_aux>>>(
        edge_u, edge_i, cnt_u, bkt_u, ovf_u, ovfc + 1);

    // ---- main stream: combine weights, then GEMMs (tensor-bound) ----
    int ctotal = KDIM * NCOMB;
    combine_w_kernel<<<(ctotal + 255) / 256, 256>>>(W_u, Wi_fc, wcu);
    combine_w_kernel<<<(ctotal + 255) / 256, 256>>>(W_i, Wu_fc, wci);

    dim3 gu(NCOMB / 128, (NU + 127) / 128);
    gemm_f16_kernel<<<gu, 256>>>(ufeat, wcu, cj_user, xu, NU);
    dim3 gi(NCOMB / 128, (NI + 127) / 128);
    gemm_f16_kernel<<<gi, 256>>>(ifeat, wci, cj_item, xi, NI);

    // ---- join: gathers need both bins and GEMMs ----
    cudaEventRecord(ev_join, s_aux);
    cudaStreamWaitEvent(0, ev_join, 0);

    // ---- fused gather + finalize, straight into d_out ----
    gather_out_kernel<NI, CAP_I, NU><<<(NI + 7) / 8, 256>>>(
        xu, cnt_i, bkt_i, ci_item, bi, out_i);
    gather_out_kernel<NU, CAP_U, NI><<<(NU + 7) / 8, 256>>>(
        xi, cnt_u, bkt_u, ci_user, bu, out_u);

    // ---- overflow fallback (normally zero work) ----
    ovf_kernel<NU><<<64, 256>>>(xu, edge_u, edge_i, ovf_i, ovfc + 0, ci_item, out_i);
    ovf_kernel<NI><<<64, 256>>>(xi, edge_i, edge_u, ovf_u, ovfc + 1, ci_user, out_u);
}